// round 11
// baseline (speedup 1.0000x reference)
#include <cuda_runtime.h>
#include <cuda_bf16.h>
#include <cuda_fp16.h>
#include <cstdint>

// Problem constants
#define Bv   2
#define Sv   2048
#define Hv   1024
#define NHv  16
#define HDv  64
#define Mv   (Bv * Sv)

// Scratch (device globals — no allocation allowed)
__device__ __nv_bfloat16 g_ahi[Mv * Hv], g_alo[Mv * Hv];       // hidden, bf16 hi/lo (Q/K proj)
__device__ __half        g_ah16[Mv * Hv], g_al16[Mv * Hv];     // hidden, fp16 hi/lo (V proj)
__device__ __nv_bfloat16 g_wqhi[Hv * Hv], g_wqlo[Hv * Hv];
__device__ __nv_bfloat16 g_wkhi[Hv * Hv], g_wklo[Hv * Hv];
__device__ __half        g_wv16[Hv * Hv];
__device__ __half        g_wo16[Hv * Hv];
__device__ __nv_bfloat16 g_qhi[Mv * Hv], g_qlo[Mv * Hv];
__device__ __nv_bfloat16 g_khi[Mv * Hv], g_klo[Mv * Hv];
__device__ __half        g_v16[Mv * Hv];
__device__ __half        g_aoh[Mv * Hv], g_aol[Mv * Hv];

__device__ __forceinline__ float elu1(float x) {
    return x > 0.f ? x + 1.f : __expf(x);
}

// ---------------------------------------------------------------------------
// helpers
// ---------------------------------------------------------------------------
__device__ __forceinline__ void splitb(float x, __nv_bfloat16& h, __nv_bfloat16& l) {
    h = __float2bfloat16(x);
    l = __float2bfloat16(x - __bfloat162float(h));
}
// bf16 mma m16n8k16
__device__ __forceinline__ void mma16(float* c, const uint32_t* a, uint32_t b0, uint32_t b1) {
    asm volatile(
        "mma.sync.aligned.m16n8k16.row.col.f32.bf16.bf16.f32 "
        "{%0,%1,%2,%3}, {%4,%5,%6,%7}, {%8,%9}, {%0,%1,%2,%3};"
        : "+f"(c[0]), "+f"(c[1]), "+f"(c[2]), "+f"(c[3])
        : "r"(a[0]), "r"(a[1]), "r"(a[2]), "r"(a[3]), "r"(b0), "r"(b1));
}
// fp16 mma m16n8k16
__device__ __forceinline__ void mma16h(float* c, const uint32_t* a, uint32_t b0, uint32_t b1) {
    asm volatile(
        "mma.sync.aligned.m16n8k16.row.col.f32.f16.f16.f32 "
        "{%0,%1,%2,%3}, {%4,%5,%6,%7}, {%8,%9}, {%0,%1,%2,%3};"
        : "+f"(c[0]), "+f"(c[1]), "+f"(c[2]), "+f"(c[3])
        : "r"(a[0]), "r"(a[1]), "r"(a[2]), "r"(a[3]), "r"(b0), "r"(b1));
}
__device__ __forceinline__ void ldsm_x4(uint32_t& r0, uint32_t& r1,
                                        uint32_t& r2, uint32_t& r3, uint32_t addr) {
    asm volatile("ldmatrix.sync.aligned.m8n8.x4.shared.b16 {%0,%1,%2,%3}, [%4];"
        : "=r"(r0), "=r"(r1), "=r"(r2), "=r"(r3) : "r"(addr));
}
__device__ __forceinline__ void ldsm_x4_trans(uint32_t& r0, uint32_t& r1,
                                              uint32_t& r2, uint32_t& r3, uint32_t addr) {
    asm volatile("ldmatrix.sync.aligned.m8n8.x4.trans.shared.b16 {%0,%1,%2,%3}, [%4];"
        : "=r"(r0), "=r"(r1), "=r"(r2), "=r"(r3) : "r"(addr));
}
__device__ __forceinline__ uint32_t smem_u32(const void* p) {
    uint32_t a;
    asm("{ .reg .u64 t; cvta.to.shared.u64 t, %1; cvt.u32.u64 %0, t; }" : "=r"(a) : "l"(p));
    return a;
}
__device__ __forceinline__ void cp_async16(uint32_t sm, const void* g) {
    asm volatile("cp.async.cg.shared.global [%0], [%1], 16;" :: "r"(sm), "l"(g));
}
#define CP_COMMIT() asm volatile("cp.async.commit_group;" ::: "memory")
template <int N>
__device__ __forceinline__ void cp_wait() {
    asm volatile("cp.async.wait_group %0;" :: "n"(N) : "memory");
}

// smem swizzles (16B-block XOR by row)
__device__ __forceinline__ int sxh(int row, int col) {     // 32-half rows (proj tiles)
    return row * 32 + ((col & 7) | ((((col >> 3) ^ (row >> 1)) & 3) << 3));
}
__device__ __forceinline__ int s64(int row, int col) {     // 64-half rows (attn Q/K)
    return row * 64 + ((col & 7) | ((((col >> 3) ^ row) & 7) << 3));
}

// ---------------------------------------------------------------------------
// Prep kernels (fused)
// ---------------------------------------------------------------------------
__global__ void split_hidden(const float* __restrict__ src)
{
    int i = (blockIdx.x * 256 + threadIdx.x) * 4;
    float4 x = *reinterpret_cast<const float4*>(src + i);
    __nv_bfloat16 bh[4], bl[4];
    splitb(x.x, bh[0], bl[0]); splitb(x.y, bh[1], bl[1]);
    splitb(x.z, bh[2], bl[2]); splitb(x.w, bh[3], bl[3]);
    __nv_bfloat162 BH0; BH0.x = bh[0]; BH0.y = bh[1];
    __nv_bfloat162 BH1; BH1.x = bh[2]; BH1.y = bh[3];
    __nv_bfloat162 BL0; BL0.x = bl[0]; BL0.y = bl[1];
    __nv_bfloat162 BL1; BL1.x = bl[2]; BL1.y = bl[3];
    *reinterpret_cast<__nv_bfloat162*>(g_ahi + i)     = BH0;
    *reinterpret_cast<__nv_bfloat162*>(g_ahi + i + 2) = BH1;
    *reinterpret_cast<__nv_bfloat162*>(g_alo + i)     = BL0;
    *reinterpret_cast<__nv_bfloat162*>(g_alo + i + 2) = BL1;
    __half hh[4], hl[4];
    hh[0] = __float2half_rn(x.x); hh[1] = __float2half_rn(x.y);
    hh[2] = __float2half_rn(x.z); hh[3] = __float2half_rn(x.w);
    hl[0] = __float2half_rn(x.x - __half2float(hh[0]));
    hl[1] = __float2half_rn(x.y - __half2float(hh[1]));
    hl[2] = __float2half_rn(x.z - __half2float(hh[2]));
    hl[3] = __float2half_rn(x.w - __half2float(hh[3]));
    __half2 HH0; HH0.x = hh[0]; HH0.y = hh[1];
    __half2 HH1; HH1.x = hh[2]; HH1.y = hh[3];
    __half2 HL0; HL0.x = hl[0]; HL0.y = hl[1];
    __half2 HL1; HL1.x = hl[2]; HL1.y = hl[3];
    *reinterpret_cast<__half2*>(g_ah16 + i)     = HH0;
    *reinterpret_cast<__half2*>(g_ah16 + i + 2) = HH1;
    *reinterpret_cast<__half2*>(g_al16 + i)     = HL0;
    *reinterpret_cast<__half2*>(g_al16 + i + 2) = HL1;
}

__global__ void split_wqk(const float* __restrict__ Wq, const float* __restrict__ Wk)
{
    const float* src = blockIdx.z ? Wk : Wq;
    __nv_bfloat16* hi = blockIdx.z ? g_wkhi : g_wqhi;
    __nv_bfloat16* lo = blockIdx.z ? g_wklo : g_wqlo;
    int i = (blockIdx.x * 256 + threadIdx.x) * 4;
    float4 x = *reinterpret_cast<const float4*>(src + i);
    __nv_bfloat16 h[4], l[4];
    splitb(x.x, h[0], l[0]); splitb(x.y, h[1], l[1]);
    splitb(x.z, h[2], l[2]); splitb(x.w, h[3], l[3]);
    __nv_bfloat162 H0; H0.x = h[0]; H0.y = h[1];
    __nv_bfloat162 H1; H1.x = h[2]; H1.y = h[3];
    __nv_bfloat162 L0; L0.x = l[0]; L0.y = l[1];
    __nv_bfloat162 L1; L1.x = l[2]; L1.y = l[3];
    *reinterpret_cast<__nv_bfloat162*>(hi + i)     = H0;
    *reinterpret_cast<__nv_bfloat162*>(hi + i + 2) = H1;
    *reinterpret_cast<__nv_bfloat162*>(lo + i)     = L0;
    *reinterpret_cast<__nv_bfloat162*>(lo + i + 2) = L1;
}

__global__ void cvt_wvo(const float* __restrict__ Wv, const float* __restrict__ Wo)
{
    const float* src = blockIdx.z ? Wo : Wv;
    __half*      dst = blockIdx.z ? g_wo16 : g_wv16;
    int i = (blockIdx.x * 256 + threadIdx.x) * 4;
    float4 x = *reinterpret_cast<const float4*>(src + i);
    *reinterpret_cast<__half2*>(dst + i)     = __float22half2_rn(make_float2(x.x, x.y));
    *reinterpret_cast<__half2*>(dst + i + 2) = __float22half2_rn(make_float2(x.z, x.w));
}

// ---------------------------------------------------------------------------
// 3xBF16 GEMM (Q/K projections): C = elu1(A @ W^T) split into bf16 planes.
// __launch_bounds__(256, 2): cap regs at 128 so 2 CTAs/SM fit (occupancy fix).
// ---------------------------------------------------------------------------
#define BK 32
#define NKC (Hv / BK)
#define STG_H (4 * 128 * 32)
#define GEMM_SMEM (3 * STG_H * 2)

__global__ __launch_bounds__(256, 2) void proj_qk()
{
    extern __shared__ char smraw[];
    uint16_t* sm = (uint16_t*)smraw;
    const int z  = blockIdx.z;
    const __nv_bfloat16* Ah = g_ahi;
    const __nv_bfloat16* Al = g_alo;
    const __nv_bfloat16* Bh = z == 0 ? g_wqhi : g_wkhi;
    const __nv_bfloat16* Bl = z == 0 ? g_wqlo : g_wklo;
    __nv_bfloat16* Chi = z == 0 ? g_qhi : g_khi;
    __nv_bfloat16* Clo = z == 0 ? g_qlo : g_klo;
    const int m0 = blockIdx.y * 128, n0 = blockIdx.x * 128;

    const int tid  = threadIdx.x;
    const int w    = tid >> 5;
    const int lane = tid & 31;
    const int g    = lane >> 2;
    const int t    = lane & 3;
    const int wm   = (w & 3) * 32;
    const int wn   = (w >> 2) * 64;

    auto load_stage = [&](int c, int s) {
        const int k0 = c * BK;
        uint16_t* st = sm + s * STG_H;
#pragma unroll
        for (int i = 0; i < 8; i++) {
            int idx = tid + i * 256;
            int arr = idx >> 9;
            int rem = idx & 511;
            int row = rem >> 2, seg = rem & 3;
            const __nv_bfloat16* gp;
            if (arr == 0)      gp = Ah + (size_t)(m0 + row) * Hv;
            else if (arr == 1) gp = Al + (size_t)(m0 + row) * Hv;
            else if (arr == 2) gp = Bh + (size_t)(n0 + row) * Hv;
            else               gp = Bl + (size_t)(n0 + row) * Hv;
            int sc = ((seg ^ (row >> 1)) & 3) * 8;
            cp_async16(smem_u32(st + arr * 4096 + row * 32 + sc), gp + k0 + seg * 8);
        }
    };

    float acc[2][8][4];
#pragma unroll
    for (int i = 0; i < 2; i++)
#pragma unroll
        for (int j = 0; j < 8; j++)
#pragma unroll
            for (int r = 0; r < 4; r++) acc[i][j][r] = 0.f;

    load_stage(0, 0); CP_COMMIT();
    load_stage(1, 1); CP_COMMIT();

    for (int c = 0; c < NKC; c++) {
        cp_wait<1>();
        __syncthreads();
        if (c + 2 < NKC) load_stage(c + 2, (c + 2) % 3);
        CP_COMMIT();

        uint16_t* st  = sm + (c % 3) * STG_H;
        uint16_t* sAh = st;
        uint16_t* sAl = st + 4096;
        uint16_t* sBh = st + 8192;
        uint16_t* sBl = st + 12288;

#pragma unroll
        for (int kb = 0; kb < 2; kb++) {
            const int koff = kb * 16 + 2 * t;
            uint32_t ah[2][4], al[2][4];
#pragma unroll
            for (int i = 0; i < 2; i++) {
                const int r = wm + i * 16 + g;
                ah[i][0] = *reinterpret_cast<uint32_t*>(&sAh[sxh(r,     koff)]);
                ah[i][1] = *reinterpret_cast<uint32_t*>(&sAh[sxh(r + 8, koff)]);
                ah[i][2] = *reinterpret_cast<uint32_t*>(&sAh[sxh(r,     koff + 8)]);
                ah[i][3] = *reinterpret_cast<uint32_t*>(&sAh[sxh(r + 8, koff + 8)]);
                al[i][0] = *reinterpret_cast<uint32_t*>(&sAl[sxh(r,     koff)]);
                al[i][1] = *reinterpret_cast<uint32_t*>(&sAl[sxh(r + 8, koff)]);
                al[i][2] = *reinterpret_cast<uint32_t*>(&sAl[sxh(r,     koff + 8)]);
                al[i][3] = *reinterpret_cast<uint32_t*>(&sAl[sxh(r + 8, koff + 8)]);
            }
#pragma unroll
            for (int j = 0; j < 8; j++) {
                const int n = wn + j * 8 + g;
                uint32_t bh0 = *reinterpret_cast<uint32_t*>(&sBh[sxh(n, koff)]);
                uint32_t bh1 = *reinterpret_cast<uint32_t*>(&sBh[sxh(n, koff + 8)]);
                uint32_t bl0 = *reinterpret_cast<uint32_t*>(&sBl[sxh(n, koff)]);
                uint32_t bl1 = *reinterpret_cast<uint32_t*>(&sBl[sxh(n, koff + 8)]);
#pragma unroll
                for (int i = 0; i < 2; i++) {
                    mma16(acc[i][j], ah[i], bl0, bl1);
                    mma16(acc[i][j], al[i], bh0, bh1);
                    mma16(acc[i][j], ah[i], bh0, bh1);
                }
            }
        }
    }

#pragma unroll
    for (int i = 0; i < 2; i++) {
#pragma unroll
        for (int rr = 0; rr < 2; rr++) {
            const int m  = m0 + wm + i * 16 + g + rr * 8;
            const int bb = m >> 11;
            const int ss = m & (Sv - 1);
#pragma unroll
            for (int j = 0; j < 8; j++) {
                float x0 = elu1(acc[i][j][rr * 2 + 0]);
                float x1 = elu1(acc[i][j][rr * 2 + 1]);
                const int n = n0 + wn + j * 8 + 2 * t;
                const int hh = n >> 6, dd = n & 63;
                const size_t o = ((size_t)(bb * NHv + hh) * Sv + ss) * HDv + dd;
                __nv_bfloat16 h0, l0, h1, l1;
                splitb(x0, h0, l0);
                splitb(x1, h1, l1);
                __nv_bfloat162 H; H.x = h0; H.y = h1;
                __nv_bfloat162 L; L.x = l0; L.y = l1;
                *reinterpret_cast<__nv_bfloat162*>(&Chi[o]) = H;
                *reinterpret_cast<__nv_bfloat162*>(&Clo[o]) = L;
            }
        }
    }
}

// ---------------------------------------------------------------------------
// 2-term FP16 GEMM: C = (Ah + Al) @ W16^T.
// OUT 1: fp32 [M,N] row-major;  OUT 3: fp16 plane [B,NH,S,HD] (V)
// ---------------------------------------------------------------------------
#define STG_O (3 * 128 * 32)
#define GEMM_O_SMEM (3 * STG_O * 2)

template <int OUT>
__device__ __forceinline__ void gemm2h_body(
    const __half* __restrict__ Ah, const __half* __restrict__ Al,
    const __half* __restrict__ W16,
    float* __restrict__ Cf, __half* __restrict__ C16,
    uint16_t* sm, int m0, int n0)
{
    const int tid  = threadIdx.x;
    const int w    = tid >> 5;
    const int lane = tid & 31;
    const int g    = lane >> 2;
    const int t    = lane & 3;
    const int wm   = (w & 3) * 32;
    const int wn   = (w >> 2) * 64;

    auto load_stage = [&](int c, int s) {
        const int k0 = c * BK;
        uint16_t* st = sm + s * STG_O;
#pragma unroll
        for (int i = 0; i < 6; i++) {
            int idx = tid + i * 256;
            int arr = idx >> 9;
            int rem = idx & 511;
            int row = rem >> 2, seg = rem & 3;
            const __half* gp;
            if (arr == 0)      gp = Ah  + (size_t)(m0 + row) * Hv;
            else if (arr == 1) gp = Al  + (size_t)(m0 + row) * Hv;
            else               gp = W16 + (size_t)(n0 + row) * Hv;
            int sc = ((seg ^ (row >> 1)) & 3) * 8;
            cp_async16(smem_u32(st + arr * 4096 + row * 32 + sc), gp + k0 + seg * 8);
        }
    };

    float acc[2][8][4];
#pragma unroll
    for (int i = 0; i < 2; i++)
#pragma unroll
        for (int j = 0; j < 8; j++)
#pragma unroll
            for (int r = 0; r < 4; r++) acc[i][j][r] = 0.f;

    load_stage(0, 0); CP_COMMIT();
    load_stage(1, 1); CP_COMMIT();

    for (int c = 0; c < NKC; c++) {
        cp_wait<1>();
        __syncthreads();
        if (c + 2 < NKC) load_stage(c + 2, (c + 2) % 3);
        CP_COMMIT();

        uint16_t* st  = sm + (c % 3) * STG_O;
        uint16_t* sAh = st;
        uint16_t* sAl = st + 4096;
        uint16_t* sW  = st + 8192;

#pragma unroll
        for (int kb = 0; kb < 2; kb++) {
            const int koff = kb * 16 + 2 * t;
            uint32_t ah[2][4], al[2][4];
#pragma unroll
            for (int i = 0; i < 2; i++) {
                const int r = wm + i * 16 + g;
                ah[i][0] = *reinterpret_cast<uint32_t*>(&sAh[sxh(r,     koff)]);
                ah[i][1] = *reinterpret_cast<uint32_t*>(&sAh[sxh(r + 8, koff)]);
                ah[i][2] = *reinterpret_cast<uint32_t*>(&sAh[sxh(r,     koff + 8)]);
                ah[i][3] = *reinterpret_cast<uint32_t*>(&sAh[sxh(r + 8, koff + 8)]);
                al[i][0] = *reinterpret_cast<uint32_t*>(&sAl[sxh(r,     koff)]);
                al[i][1] = *reinterpret_cast<uint32_t*>(&sAl[sxh(r + 8, koff)]);
                al[i][2] = *reinterpret_cast<uint32_t*>(&sAl[sxh(r,     koff + 8)]);
                al[i][3] = *reinterpret_cast<uint32_t*>(&sAl[sxh(r + 8, koff + 8)]);
            }
#pragma unroll
            for (int j = 0; j < 8; j++) {
                const int n = wn + j * 8 + g;
                uint32_t b0 = *reinterpret_cast<uint32_t*>(&sW[sxh(n, koff)]);
                uint32_t b1 = *reinterpret_cast<uint32_t*>(&sW[sxh(n, koff + 8)]);
#pragma unroll
                for (int i = 0; i < 2; i++) {
                    mma16h(acc[i][j], al[i], b0, b1);
                    mma16h(acc[i][j], ah[i], b0, b1);
                }
            }
        }
    }

#pragma unroll
    for (int i = 0; i < 2; i++) {
#pragma unroll
        for (int rr = 0; rr < 2; rr++) {
            const int m  = m0 + wm + i * 16 + g + rr * 8;
            const int bb = m >> 11;
            const int ss = m & (Sv - 1);
#pragma unroll
            for (int j = 0; j < 8; j++) {
                float x0 = acc[i][j][rr * 2 + 0];
                float x1 = acc[i][j][rr * 2 + 1];
                const int n = n0 + wn + j * 8 + 2 * t;
                if (OUT == 1) {
                    *reinterpret_cast<float2*>(&Cf[(size_t)m * Hv + n]) =
                        make_float2(x0, x1);
                } else {
                    const int hh = n >> 6, dd = n & 63;
                    const size_t o = ((size_t)(bb * NHv + hh) * Sv + ss) * HDv + dd;
                    *reinterpret_cast<__half2*>(&C16[o]) =
                        __float22half2_rn(make_float2(x0, x1));
                }
            }
        }
    }
}

__global__ __launch_bounds__(256, 2) void proj_v()
{
    extern __shared__ char smraw[];
    gemm2h_body<3>(g_ah16, g_al16, g_wv16, nullptr, g_v16,
                   (uint16_t*)smraw, blockIdx.y * 128, blockIdx.x * 128);
}

__global__ __launch_bounds__(256, 2) void proj_o(float* __restrict__ out)
{
    extern __shared__ char smraw[];
    gemm2h_body<1>(g_aoh, g_aol, g_wo16, out, nullptr,
                   (uint16_t*)smraw, blockIdx.y * 128, blockIdx.x * 128);
}

// ---------------------------------------------------------------------------
// Flash attention: scores 3xBF16 via ldmatrix frags; PV 2-term FP16;
// cp.async double-buffered K/V/mask tiles; exp on MUFU.
// ---------------------------------------------------------------------------
#define VPITCH 72
#define KVTILE (64 * 64 + 64 * 64 + 64 * VPITCH)    // 12800 halfs
#define OFF_KV (2 * 128 * 64)                       // 16384
#define OFF_END (OFF_KV + 2 * KVTILE)               // 41984 halfs
#define ATTN_SMEM (OFF_END * 2 + 2 * 64 * 4)        // 84480 B

__global__ __launch_bounds__(256, 2) void attn_mma(const int* __restrict__ mask)
{
    extern __shared__ char shraw[];
    uint16_t* Qh = (uint16_t*)shraw;
    uint16_t* Ql = Qh + 128 * 64;
    uint16_t* KV = Qh + OFF_KV;
    int* Msbase  = (int*)(Qh + OFF_END);

    const int bb = blockIdx.z;
    const int hh = blockIdx.y;
    const int q0 = blockIdx.x * 128;

    const size_t hb = (size_t)(bb * NHv + hh) * Sv;
    const __nv_bfloat16* Qhg = g_qhi + (hb + q0) * HDv;
    const __nv_bfloat16* Qlg = g_qlo + (hb + q0) * HDv;
    const __nv_bfloat16* Khg = g_khi + hb * HDv;
    const __nv_bfloat16* Klg = g_klo + hb * HDv;
    const __half*        Vg  = g_v16 + hb * HDv;

    const int tid  = threadIdx.x;
    const int w    = tid >> 5;
    const int lane = tid & 31;
    const int g    = lane >> 2;
    const int t    = lane & 3;
    const int qb   = w * 16;

    const int lrow8 = lane & 7;
    const int half8 = (lane >> 3) & 1;
    const int cbsel = lane >> 4;
    const int qrowL = qb + half8 * 8 + lrow8;
    const uint32_t qh_base = smem_u32(Qh);
    const uint32_t ql_base = smem_u32(Ql);
    const int ltile = lane >> 3;
    const int v_row_base = (ltile & 1) * 8 + lrow8;
    const int v_col_half = (ltile >> 1) * 8;

    // load Q tiles (hi/lo)
#pragma unroll
    for (int i = 0; i < 8; i++) {
        int idx = tid + i * 256;
        int row = idx >> 4, q4 = (idx & 15) * 4;
        int so = s64(row, q4);
        *reinterpret_cast<uint2*>(&Qh[so]) =
            *reinterpret_cast<const uint2*>(&Qhg[row * HDv + q4]);
        *reinterpret_cast<uint2*>(&Ql[so]) =
            *reinterpret_cast<const uint2*>(&Qlg[row * HDv + q4]);
    }

    auto prefetch = [&](int tt, int bbuf) {
        const int k0 = tt * 64;
        uint16_t* kv = KV + bbuf * KVTILE;
#pragma unroll
        for (int i = 0; i < 6; i++) {
            int idx = tid + i * 256;
            if (idx < 512) {
                int row = idx >> 3, seg = idx & 7;
                cp_async16(smem_u32(kv + row * 64 + ((seg ^ row) & 7) * 8),
                           Khg + (size_t)(k0 + row) * HDv + seg * 8);
            } else if (idx < 1024) {
                int rem = idx - 512;
                int row = rem >> 3, seg = rem & 7;
                cp_async16(smem_u32(kv + 4096 + row * 64 + ((seg ^ row) & 7) * 8),
                           Klg + (size_t)(k0 + row) * HDv + seg * 8);
            } else {
                int rem = idx - 1024;
                int row = rem >> 3, seg = rem & 7;
                cp_async16(smem_u32(kv + 8192 + row * VPITCH + seg * 8),
                           Vg + (size_t)(k0 + row) * HDv + seg * 8);
            }
        }
        if (tid < 16)
            cp_async16(smem_u32(Msbase + bbuf * 64 + tid * 4),
                       mask + bb * Sv + k0 + tid * 4);
    };

    float oacc[8][4];
#pragma unroll
    for (int j = 0; j < 8; j++)
#pragma unroll
        for (int r = 0; r < 4; r++) oacc[j][r] = 0.f;
    float m0r = -1e30f, m1r = -1e30f, l0r = 0.f, l1r = 0.f;

    prefetch(0, 0);
    CP_COMMIT();

    for (int tk = 0; tk < Sv / 64; tk++) {
        const int b = tk & 1;
        cp_wait<0>();
        __syncthreads();
        if (tk + 1 < Sv / 64) prefetch(tk + 1, b ^ 1);
        CP_COMMIT();

        const uint32_t khb = smem_u32(KV + b * KVTILE);
        const uint32_t klb = khb + 4096 * 2;
        const uint32_t vhb = khb + 8192 * 2;
        const int* Ms = Msbase + b * 64;

        // ---- scores (3xBF16, ldmatrix frags) ----
        float sacc[8][4];
#pragma unroll
        for (int j = 0; j < 8; j++)
#pragma unroll
            for (int r = 0; r < 4; r++) sacc[j][r] = 0.f;

#pragma unroll
        for (int kb = 0; kb < 4; kb++) {
            const int cb = kb * 2 + cbsel;
            const uint32_t qoff = (uint32_t)(qrowL * 64 + ((cb ^ qrowL) & 7) * 8) * 2;
            uint32_t ah[4], al[4];
            ldsm_x4(ah[0], ah[1], ah[2], ah[3], qh_base + qoff);
            ldsm_x4(al[0], al[1], al[2], al[3], ql_base + qoff);
#pragma unroll
            for (int p = 0; p < 4; p++) {
                const int krowL = p * 16 + half8 * 8 + lrow8;
                const uint32_t koff =
                    (uint32_t)(krowL * 64 + ((cb ^ krowL) & 7) * 8) * 2;
                uint32_t kh0, kh1, kh2, kh3, kl0, kl1, kl2, kl3;
                ldsm_x4(kh0, kh1, kh2, kh3, khb + koff);
                ldsm_x4(kl0, kl1, kl2, kl3, klb + koff);
                mma16(sacc[2 * p],     ah, kl0, kl2);
                mma16(sacc[2 * p],     al, kh0, kh2);
                mma16(sacc[2 * p],     ah, kh0, kh2);
                mma16(sacc[2 * p + 1], ah, kl1, kl3);
                mma16(sacc[2 * p + 1], al, kh1, kh3);
                mma16(sacc[2 * p + 1], ah, kh1, kh3);
            }
        }

        // ---- mask ----
#pragma unroll
        for (int j = 0; j < 8; j++) {
            if (Ms[j * 8 + 2 * t] == 0)     { sacc[j][0] = -1e30f; sacc[j][2] = -1e30f; }
            if (Ms[j * 8 + 2 * t + 1] == 0) { sacc[j][1] = -1e30f; sacc[j][3] = -1e30f; }
        }

        // ---- online softmax (exp on MUFU) ----
        float mx0 = -1e30f, mx1 = -1e30f;
#pragma unroll
        for (int j = 0; j < 8; j++) {
            mx0 = fmaxf(mx0, fmaxf(sacc[j][0], sacc[j][1]));
            mx1 = fmaxf(mx1, fmaxf(sacc[j][2], sacc[j][3]));
        }
        mx0 = fmaxf(mx0, __shfl_xor_sync(0xffffffffu, mx0, 1));
        mx0 = fmaxf(mx0, __shfl_xor_sync(0xffffffffu, mx0, 2));
        mx1 = fmaxf(mx1, __shfl_xor_sync(0xffffffffu, mx1, 1));
        mx1 = fmaxf(mx1, __shfl_xor_sync(0xffffffffu, mx1, 2));

        const float mn0 = fmaxf(m0r, mx0);
        const float mn1 = fmaxf(m1r, mx1);
        const float a0  = __expf(m0r - mn0);
        const float a1  = __expf(m1r - mn1);
        m0r = mn0; m1r = mn1;

        float s0 = 0.f, s1 = 0.f;
#pragma unroll
        for (int j = 0; j < 8; j++) {
            sacc[j][0] = __expf(sacc[j][0] - mn0);
            sacc[j][1] = __expf(sacc[j][1] - mn0);
            sacc[j][2] = __expf(sacc[j][2] - mn1);
            sacc[j][3] = __expf(sacc[j][3] - mn1);
            s0 += sacc[j][0] + sacc[j][1];
            s1 += sacc[j][2] + sacc[j][3];
        }
        s0 += __shfl_xor_sync(0xffffffffu, s0, 1);
        s0 += __shfl_xor_sync(0xffffffffu, s0, 2);
        s1 += __shfl_xor_sync(0xffffffffu, s1, 1);
        s1 += __shfl_xor_sync(0xffffffffu, s1, 2);
        l0r = l0r * a0 + s0;
        l1r = l1r * a1 + s1;
#pragma unroll
        for (int j = 0; j < 8; j++) {
            oacc[j][0] *= a0; oacc[j][1] *= a0;
            oacc[j][2] *= a1; oacc[j][3] *= a1;
        }

        // ---- O += P @ V  (2-term FP16) ----
#pragma unroll
        for (int jp2 = 0; jp2 < 4; jp2++) {
            uint32_t ap_h[4], ap_l[4];
#pragma unroll
            for (int half = 0; half < 2; half++) {
                const float* c = sacc[2 * jp2 + half];
                __half2 h01 = __float22half2_rn(make_float2(c[0], c[1]));
                __half2 h23 = __float22half2_rn(make_float2(c[2], c[3]));
                float2 f01 = __half22float2(h01);
                float2 f23 = __half22float2(h23);
                __half2 l01 = __float22half2_rn(make_float2(c[0] - f01.x, c[1] - f01.y));
                __half2 l23 = __float22half2_rn(make_float2(c[2] - f23.x, c[3] - f23.y));
                ap_h[half == 0 ? 0 : 2] = *reinterpret_cast<uint32_t*>(&h01);
                ap_h[half == 0 ? 1 : 3] = *reinterpret_cast<uint32_t*>(&h23);
                ap_l[half == 0 ? 0 : 2] = *reinterpret_cast<uint32_t*>(&l01);
                ap_l[half == 0 ? 1 : 3] = *reinterpret_cast<uint32_t*>(&l23);
            }
            const uint32_t vrow =
                (uint32_t)((jp2 * 16 + v_row_base) * VPITCH * 2 + v_col_half * 2);
#pragma unroll
            for (int jp = 0; jp < 4; jp++) {
                uint32_t b0, b1, b2, b3;
                ldsm_x4_trans(b0, b1, b2, b3, vhb + vrow + jp * 32);
                mma16h(oacc[jp * 2 + 0], ap_l, b0, b1);
                mma16h(oacc[jp * 2 + 0], ap_h, b0, b1);
                mma16h(oacc[jp * 2 + 1], ap_l, b2, b3);
                mma16h(oacc[jp * 2 + 1], ap_h, b2, b3);
            }
        }
    }

    // ---- normalize + split-write fp16 hi/lo planes [B,S,H] ----
    const float i0 = 1.f / l0r;
    const float i1 = 1.f / l1r;
    const int r0 = q0 + qb + g;
    const int r1 = r0 + 8;
#pragma unroll
    for (int j = 0; j < 8; j++) {
        const int col = hh * 64 + j * 8 + 2 * t;
        float y0 = oacc[j][0] * i0, y1 = oacc[j][1] * i0;
        float y2 = oacc[j][2] * i1, y3 = oacc[j][3] * i1;
        __half2 H0 = __float22half2_rn(make_float2(y0, y1));
        float2 F0 = __half22float2(H0);
        __half2 L0 = __float22half2_rn(make_float2(y0 - F0.x, y1 - F0.y));
        __half2 H1 = __float22half2_rn(make_float2(y2, y3));
        float2 F1 = __half22float2(H1);
        __half2 L1 = __float22half2_rn(make_float2(y2 - F1.x, y3 - F1.y));
        const size_t o0 = ((size_t)bb * Sv + r0) * Hv + col;
        const size_t o1 = ((size_t)bb * Sv + r1) * Hv + col;
        *reinterpret_cast<__half2*>(&g_aoh[o0]) = H0;
        *reinterpret_cast<__half2*>(&g_aol[o0]) = L0;
        *reinterpret_cast<__half2*>(&g_aoh[o1]) = H1;
        *reinterpret_cast<__half2*>(&g_aol[o1]) = L1;
    }
}

// ---------------------------------------------------------------------------
extern "C" void kernel_launch(void* const* d_in, const int* in_sizes, int n_in,
                              void* d_out, int out_size)
{
    const float* hs   = (const float*)d_in[0];
    const int*   mask = (const int*)d_in[1];
    const float* Wq   = (const float*)d_in[2];
    const float* Wk   = (const float*)d_in[3];
    const float* Wv   = (const float*)d_in[4];
    const float* Wo   = (const float*)d_in[5];
    float*       out  = (float*)d_out;

    cudaFuncSetAttribute(proj_qk, cudaFuncAttributeMaxDynamicSharedMemorySize, GEMM_SMEM);
    cudaFuncSetAttribute(proj_v,  cudaFuncAttributeMaxDynamicSharedMemorySize, GEMM_O_SMEM);
    cudaFuncSetAttribute(proj_o,  cudaFuncAttributeMaxDynamicSharedMemorySize, GEMM_O_SMEM);
    cudaFuncSetAttribute(attn_mma, cudaFuncAttributeMaxDynamicSharedMemorySize, ATTN_SMEM);

    split_hidden<<<Mv * Hv / 1024, 256>>>(hs);
    split_wqk<<<dim3(Hv * Hv / 1024, 1, 2), 256>>>(Wq, Wk);
    cvt_wvo<<<dim3(Hv * Hv / 1024, 1, 2), 256>>>(Wv, Wo);

    proj_qk<<<dim3(Hv / 128, Mv / 128, 2), 256, GEMM_SMEM>>>();
    proj_v<<<dim3(Hv / 128, Mv / 128), 256, GEMM_O_SMEM>>>();

    attn_mma<<<dim3(Sv / 128, NHv, Bv), 256, ATTN_SMEM>>>(mask);

    proj_o<<<dim3(Hv / 128, Mv / 128), 256, GEMM_O_SMEM>>>(out);
}

// round 12
// speedup vs baseline: 1.0883x; 1.0883x over previous
#include <cuda_runtime.h>
#include <cuda_bf16.h>
#include <cuda_fp16.h>
#include <cstdint>

// Problem constants
#define Bv   2
#define Sv   2048
#define Hv   1024
#define NHv  16
#define HDv  64
#define Mv   (Bv * Sv)

// Scratch (device globals — no allocation allowed)
__device__ __nv_bfloat16 g_ahi[Mv * Hv], g_alo[Mv * Hv];       // hidden, bf16 hi/lo (Q/K proj)
__device__ __half        g_ah16[Mv * Hv], g_al16[Mv * Hv];     // hidden, fp16 hi/lo (V proj)
__device__ __nv_bfloat16 g_wqhi[Hv * Hv], g_wqlo[Hv * Hv];
__device__ __nv_bfloat16 g_wkhi[Hv * Hv], g_wklo[Hv * Hv];
__device__ __half        g_wv16[Hv * Hv];
__device__ __half        g_wo16[Hv * Hv];
__device__ __nv_bfloat16 g_qhi[Mv * Hv], g_qlo[Mv * Hv];
__device__ __nv_bfloat16 g_khi[Mv * Hv], g_klo[Mv * Hv];
__device__ __half        g_v16[Mv * Hv];
__device__ __half        g_aoh[Mv * Hv], g_aol[Mv * Hv];

__device__ __forceinline__ float elu1(float x) {
    return x > 0.f ? x + 1.f : __expf(x);
}

// ---------------------------------------------------------------------------
// helpers
// ---------------------------------------------------------------------------
__device__ __forceinline__ void splitb(float x, __nv_bfloat16& h, __nv_bfloat16& l) {
    h = __float2bfloat16(x);
    l = __float2bfloat16(x - __bfloat162float(h));
}
// bf16 mma m16n8k16
__device__ __forceinline__ void mma16(float* c, const uint32_t* a, uint32_t b0, uint32_t b1) {
    asm volatile(
        "mma.sync.aligned.m16n8k16.row.col.f32.bf16.bf16.f32 "
        "{%0,%1,%2,%3}, {%4,%5,%6,%7}, {%8,%9}, {%0,%1,%2,%3};"
        : "+f"(c[0]), "+f"(c[1]), "+f"(c[2]), "+f"(c[3])
        : "r"(a[0]), "r"(a[1]), "r"(a[2]), "r"(a[3]), "r"(b0), "r"(b1));
}
// fp16 mma m16n8k16
__device__ __forceinline__ void mma16h(float* c, const uint32_t* a, uint32_t b0, uint32_t b1) {
    asm volatile(
        "mma.sync.aligned.m16n8k16.row.col.f32.f16.f16.f32 "
        "{%0,%1,%2,%3}, {%4,%5,%6,%7}, {%8,%9}, {%0,%1,%2,%3};"
        : "+f"(c[0]), "+f"(c[1]), "+f"(c[2]), "+f"(c[3])
        : "r"(a[0]), "r"(a[1]), "r"(a[2]), "r"(a[3]), "r"(b0), "r"(b1));
}
__device__ __forceinline__ void ldsm_x4(uint32_t& r0, uint32_t& r1,
                                        uint32_t& r2, uint32_t& r3, uint32_t addr) {
    asm volatile("ldmatrix.sync.aligned.m8n8.x4.shared.b16 {%0,%1,%2,%3}, [%4];"
        : "=r"(r0), "=r"(r1), "=r"(r2), "=r"(r3) : "r"(addr));
}
__device__ __forceinline__ void ldsm_x4_trans(uint32_t& r0, uint32_t& r1,
                                              uint32_t& r2, uint32_t& r3, uint32_t addr) {
    asm volatile("ldmatrix.sync.aligned.m8n8.x4.trans.shared.b16 {%0,%1,%2,%3}, [%4];"
        : "=r"(r0), "=r"(r1), "=r"(r2), "=r"(r3) : "r"(addr));
}
__device__ __forceinline__ uint32_t smem_u32(const void* p) {
    uint32_t a;
    asm("{ .reg .u64 t; cvta.to.shared.u64 t, %1; cvt.u32.u64 %0, t; }" : "=r"(a) : "l"(p));
    return a;
}
__device__ __forceinline__ void cp_async16(uint32_t sm, const void* g) {
    asm volatile("cp.async.cg.shared.global [%0], [%1], 16;" :: "r"(sm), "l"(g));
}
#define CP_COMMIT() asm volatile("cp.async.commit_group;" ::: "memory")
template <int N>
__device__ __forceinline__ void cp_wait() {
    asm volatile("cp.async.wait_group %0;" :: "n"(N) : "memory");
}

// smem swizzles (16B-block XOR by row)
__device__ __forceinline__ int sxh(int row, int col) {     // 32-half rows (proj tiles)
    return row * 32 + ((col & 7) | ((((col >> 3) ^ (row >> 1)) & 3) << 3));
}
__device__ __forceinline__ int s64(int row, int col) {     // 64-half rows (attn Q/K)
    return row * 64 + ((col & 7) | ((((col >> 3) ^ row) & 7) << 3));
}

// ---------------------------------------------------------------------------
// Prep kernels (fused)
// ---------------------------------------------------------------------------
__global__ void split_hidden(const float* __restrict__ src)
{
    int i = (blockIdx.x * 256 + threadIdx.x) * 4;
    float4 x = *reinterpret_cast<const float4*>(src + i);
    __nv_bfloat16 bh[4], bl[4];
    splitb(x.x, bh[0], bl[0]); splitb(x.y, bh[1], bl[1]);
    splitb(x.z, bh[2], bl[2]); splitb(x.w, bh[3], bl[3]);
    __nv_bfloat162 BH0; BH0.x = bh[0]; BH0.y = bh[1];
    __nv_bfloat162 BH1; BH1.x = bh[2]; BH1.y = bh[3];
    __nv_bfloat162 BL0; BL0.x = bl[0]; BL0.y = bl[1];
    __nv_bfloat162 BL1; BL1.x = bl[2]; BL1.y = bl[3];
    *reinterpret_cast<__nv_bfloat162*>(g_ahi + i)     = BH0;
    *reinterpret_cast<__nv_bfloat162*>(g_ahi + i + 2) = BH1;
    *reinterpret_cast<__nv_bfloat162*>(g_alo + i)     = BL0;
    *reinterpret_cast<__nv_bfloat162*>(g_alo + i + 2) = BL1;
    __half hh[4], hl[4];
    hh[0] = __float2half_rn(x.x); hh[1] = __float2half_rn(x.y);
    hh[2] = __float2half_rn(x.z); hh[3] = __float2half_rn(x.w);
    hl[0] = __float2half_rn(x.x - __half2float(hh[0]));
    hl[1] = __float2half_rn(x.y - __half2float(hh[1]));
    hl[2] = __float2half_rn(x.z - __half2float(hh[2]));
    hl[3] = __float2half_rn(x.w - __half2float(hh[3]));
    __half2 HH0; HH0.x = hh[0]; HH0.y = hh[1];
    __half2 HH1; HH1.x = hh[2]; HH1.y = hh[3];
    __half2 HL0; HL0.x = hl[0]; HL0.y = hl[1];
    __half2 HL1; HL1.x = hl[2]; HL1.y = hl[3];
    *reinterpret_cast<__half2*>(g_ah16 + i)     = HH0;
    *reinterpret_cast<__half2*>(g_ah16 + i + 2) = HH1;
    *reinterpret_cast<__half2*>(g_al16 + i)     = HL0;
    *reinterpret_cast<__half2*>(g_al16 + i + 2) = HL1;
}

__global__ void split_wqk(const float* __restrict__ Wq, const float* __restrict__ Wk)
{
    const float* src = blockIdx.z ? Wk : Wq;
    __nv_bfloat16* hi = blockIdx.z ? g_wkhi : g_wqhi;
    __nv_bfloat16* lo = blockIdx.z ? g_wklo : g_wqlo;
    int i = (blockIdx.x * 256 + threadIdx.x) * 4;
    float4 x = *reinterpret_cast<const float4*>(src + i);
    __nv_bfloat16 h[4], l[4];
    splitb(x.x, h[0], l[0]); splitb(x.y, h[1], l[1]);
    splitb(x.z, h[2], l[2]); splitb(x.w, h[3], l[3]);
    __nv_bfloat162 H0; H0.x = h[0]; H0.y = h[1];
    __nv_bfloat162 H1; H1.x = h[2]; H1.y = h[3];
    __nv_bfloat162 L0; L0.x = l[0]; L0.y = l[1];
    __nv_bfloat162 L1; L1.x = l[2]; L1.y = l[3];
    *reinterpret_cast<__nv_bfloat162*>(hi + i)     = H0;
    *reinterpret_cast<__nv_bfloat162*>(hi + i + 2) = H1;
    *reinterpret_cast<__nv_bfloat162*>(lo + i)     = L0;
    *reinterpret_cast<__nv_bfloat162*>(lo + i + 2) = L1;
}

__global__ void cvt_wvo(const float* __restrict__ Wv, const float* __restrict__ Wo)
{
    const float* src = blockIdx.z ? Wo : Wv;
    __half*      dst = blockIdx.z ? g_wo16 : g_wv16;
    int i = (blockIdx.x * 256 + threadIdx.x) * 4;
    float4 x = *reinterpret_cast<const float4*>(src + i);
    *reinterpret_cast<__half2*>(dst + i)     = __float22half2_rn(make_float2(x.x, x.y));
    *reinterpret_cast<__half2*>(dst + i + 2) = __float22half2_rn(make_float2(x.z, x.w));
}

// ---------------------------------------------------------------------------
// 3xBF16 GEMM (Q/K projections): C = elu1(A @ W^T) split into bf16 planes.
// Tile 128x64, warp tile 32x32 (acc=32 regs) -> 2 CTAs/SM without spills.
// ---------------------------------------------------------------------------
#define BK 32
#define NKC (Hv / BK)
#define QK_STG_H (2 * 128 * 32 + 2 * 64 * 32)       // 12288 halfs / stage
#define QK_SMEM (3 * QK_STG_H * 2)                   // 73728 B

__global__ __launch_bounds__(256, 2) void proj_qk()
{
    extern __shared__ char smraw[];
    uint16_t* sm = (uint16_t*)smraw;
    const int z  = blockIdx.z;
    const __nv_bfloat16* Ah = g_ahi;
    const __nv_bfloat16* Al = g_alo;
    const __nv_bfloat16* Bh = z == 0 ? g_wqhi : g_wkhi;
    const __nv_bfloat16* Bl = z == 0 ? g_wqlo : g_wklo;
    __nv_bfloat16* Chi = z == 0 ? g_qhi : g_khi;
    __nv_bfloat16* Clo = z == 0 ? g_qlo : g_klo;
    const int m0 = blockIdx.y * 128, n0 = blockIdx.x * 64;

    const int tid  = threadIdx.x;
    const int w    = tid >> 5;
    const int lane = tid & 31;
    const int g    = lane >> 2;
    const int t    = lane & 3;
    const int wm   = (w & 3) * 32;
    const int wn   = (w >> 2) * 32;

    auto load_stage = [&](int c, int s) {
        const int k0 = c * BK;
        uint16_t* st = sm + s * QK_STG_H;
#pragma unroll
        for (int i = 0; i < 6; i++) {
            int idx = tid + i * 256;                 // 0..1535
            const __nv_bfloat16* gp;
            int row, seg, base;
            if (idx < 512)        { row = idx >> 2;          seg = idx & 3;
                                    gp = Ah + (size_t)(m0 + row) * Hv; base = 0; }
            else if (idx < 1024)  { int r2 = idx - 512;  row = r2 >> 2; seg = r2 & 3;
                                    gp = Al + (size_t)(m0 + row) * Hv; base = 4096; }
            else if (idx < 1280)  { int r2 = idx - 1024; row = r2 >> 2; seg = r2 & 3;
                                    gp = Bh + (size_t)(n0 + row) * Hv; base = 8192; }
            else                  { int r2 = idx - 1280; row = r2 >> 2; seg = r2 & 3;
                                    gp = Bl + (size_t)(n0 + row) * Hv; base = 10240; }
            int sc = ((seg ^ (row >> 1)) & 3) * 8;
            cp_async16(smem_u32(st + base + row * 32 + sc), gp + k0 + seg * 8);
        }
    };

    float acc[2][4][4];
#pragma unroll
    for (int i = 0; i < 2; i++)
#pragma unroll
        for (int j = 0; j < 4; j++)
#pragma unroll
            for (int r = 0; r < 4; r++) acc[i][j][r] = 0.f;

    load_stage(0, 0); CP_COMMIT();
    load_stage(1, 1); CP_COMMIT();

    for (int c = 0; c < NKC; c++) {
        cp_wait<1>();
        __syncthreads();
        if (c + 2 < NKC) load_stage(c + 2, (c + 2) % 3);
        CP_COMMIT();

        uint16_t* st  = sm + (c % 3) * QK_STG_H;
        uint16_t* sAh = st;
        uint16_t* sAl = st + 4096;
        uint16_t* sBh = st + 8192;
        uint16_t* sBl = st + 10240;

#pragma unroll
        for (int kb = 0; kb < 2; kb++) {
            const int koff = kb * 16 + 2 * t;
            uint32_t ah[2][4], al[2][4];
#pragma unroll
            for (int i = 0; i < 2; i++) {
                const int r = wm + i * 16 + g;
                ah[i][0] = *reinterpret_cast<uint32_t*>(&sAh[sxh(r,     koff)]);
                ah[i][1] = *reinterpret_cast<uint32_t*>(&sAh[sxh(r + 8, koff)]);
                ah[i][2] = *reinterpret_cast<uint32_t*>(&sAh[sxh(r,     koff + 8)]);
                ah[i][3] = *reinterpret_cast<uint32_t*>(&sAh[sxh(r + 8, koff + 8)]);
                al[i][0] = *reinterpret_cast<uint32_t*>(&sAl[sxh(r,     koff)]);
                al[i][1] = *reinterpret_cast<uint32_t*>(&sAl[sxh(r + 8, koff)]);
                al[i][2] = *reinterpret_cast<uint32_t*>(&sAl[sxh(r,     koff + 8)]);
                al[i][3] = *reinterpret_cast<uint32_t*>(&sAl[sxh(r + 8, koff + 8)]);
            }
#pragma unroll
            for (int j = 0; j < 4; j++) {
                const int n = wn + j * 8 + g;
                uint32_t bh0 = *reinterpret_cast<uint32_t*>(&sBh[sxh(n, koff)]);
                uint32_t bh1 = *reinterpret_cast<uint32_t*>(&sBh[sxh(n, koff + 8)]);
                uint32_t bl0 = *reinterpret_cast<uint32_t*>(&sBl[sxh(n, koff)]);
                uint32_t bl1 = *reinterpret_cast<uint32_t*>(&sBl[sxh(n, koff + 8)]);
#pragma unroll
                for (int i = 0; i < 2; i++) {
                    mma16(acc[i][j], ah[i], bl0, bl1);
                    mma16(acc[i][j], al[i], bh0, bh1);
                    mma16(acc[i][j], ah[i], bh0, bh1);
                }
            }
        }
    }

#pragma unroll
    for (int i = 0; i < 2; i++) {
#pragma unroll
        for (int rr = 0; rr < 2; rr++) {
            const int m  = m0 + wm + i * 16 + g + rr * 8;
            const int bb = m >> 11;
            const int ss = m & (Sv - 1);
#pragma unroll
            for (int j = 0; j < 4; j++) {
                float x0 = elu1(acc[i][j][rr * 2 + 0]);
                float x1 = elu1(acc[i][j][rr * 2 + 1]);
                const int n = n0 + wn + j * 8 + 2 * t;
                const int hh = n >> 6, dd = n & 63;
                const size_t o = ((size_t)(bb * NHv + hh) * Sv + ss) * HDv + dd;
                __nv_bfloat16 h0, l0, h1, l1;
                splitb(x0, h0, l0);
                splitb(x1, h1, l1);
                __nv_bfloat162 H; H.x = h0; H.y = h1;
                __nv_bfloat162 L; L.x = l0; L.y = l1;
                *reinterpret_cast<__nv_bfloat162*>(&Chi[o]) = H;
                *reinterpret_cast<__nv_bfloat162*>(&Clo[o]) = L;
            }
        }
    }
}

// ---------------------------------------------------------------------------
// 2-term FP16 GEMM: C = (Ah + Al) @ W16^T.  (round-10 exact form, no min-cta)
// OUT 1: fp32 [M,N] row-major;  OUT 3: fp16 plane [B,NH,S,HD] (V)
// ---------------------------------------------------------------------------
#define STG_O (3 * 128 * 32)
#define GEMM_O_SMEM (3 * STG_O * 2)

template <int OUT>
__device__ __forceinline__ void gemm2h_body(
    const __half* __restrict__ Ah, const __half* __restrict__ Al,
    const __half* __restrict__ W16,
    float* __restrict__ Cf, __half* __restrict__ C16,
    uint16_t* sm, int m0, int n0)
{
    const int tid  = threadIdx.x;
    const int w    = tid >> 5;
    const int lane = tid & 31;
    const int g    = lane >> 2;
    const int t    = lane & 3;
    const int wm   = (w & 3) * 32;
    const int wn   = (w >> 2) * 64;

    auto load_stage = [&](int c, int s) {
        const int k0 = c * BK;
        uint16_t* st = sm + s * STG_O;
#pragma unroll
        for (int i = 0; i < 6; i++) {
            int idx = tid + i * 256;
            int arr = idx >> 9;
            int rem = idx & 511;
            int row = rem >> 2, seg = rem & 3;
            const __half* gp;
            if (arr == 0)      gp = Ah  + (size_t)(m0 + row) * Hv;
            else if (arr == 1) gp = Al  + (size_t)(m0 + row) * Hv;
            else               gp = W16 + (size_t)(n0 + row) * Hv;
            int sc = ((seg ^ (row >> 1)) & 3) * 8;
            cp_async16(smem_u32(st + arr * 4096 + row * 32 + sc), gp + k0 + seg * 8);
        }
    };

    float acc[2][8][4];
#pragma unroll
    for (int i = 0; i < 2; i++)
#pragma unroll
        for (int j = 0; j < 8; j++)
#pragma unroll
            for (int r = 0; r < 4; r++) acc[i][j][r] = 0.f;

    load_stage(0, 0); CP_COMMIT();
    load_stage(1, 1); CP_COMMIT();

    for (int c = 0; c < NKC; c++) {
        cp_wait<1>();
        __syncthreads();
        if (c + 2 < NKC) load_stage(c + 2, (c + 2) % 3);
        CP_COMMIT();

        uint16_t* st  = sm + (c % 3) * STG_O;
        uint16_t* sAh = st;
        uint16_t* sAl = st + 4096;
        uint16_t* sW  = st + 8192;

#pragma unroll
        for (int kb = 0; kb < 2; kb++) {
            const int koff = kb * 16 + 2 * t;
            uint32_t ah[2][4], al[2][4];
#pragma unroll
            for (int i = 0; i < 2; i++) {
                const int r = wm + i * 16 + g;
                ah[i][0] = *reinterpret_cast<uint32_t*>(&sAh[sxh(r,     koff)]);
                ah[i][1] = *reinterpret_cast<uint32_t*>(&sAh[sxh(r + 8, koff)]);
                ah[i][2] = *reinterpret_cast<uint32_t*>(&sAh[sxh(r,     koff + 8)]);
                ah[i][3] = *reinterpret_cast<uint32_t*>(&sAh[sxh(r + 8, koff + 8)]);
                al[i][0] = *reinterpret_cast<uint32_t*>(&sAl[sxh(r,     koff)]);
                al[i][1] = *reinterpret_cast<uint32_t*>(&sAl[sxh(r + 8, koff)]);
                al[i][2] = *reinterpret_cast<uint32_t*>(&sAl[sxh(r,     koff + 8)]);
                al[i][3] = *reinterpret_cast<uint32_t*>(&sAl[sxh(r + 8, koff + 8)]);
            }
#pragma unroll
            for (int j = 0; j < 8; j++) {
                const int n = wn + j * 8 + g;
                uint32_t b0 = *reinterpret_cast<uint32_t*>(&sW[sxh(n, koff)]);
                uint32_t b1 = *reinterpret_cast<uint32_t*>(&sW[sxh(n, koff + 8)]);
#pragma unroll
                for (int i = 0; i < 2; i++) {
                    mma16h(acc[i][j], al[i], b0, b1);
                    mma16h(acc[i][j], ah[i], b0, b1);
                }
            }
        }
    }

#pragma unroll
    for (int i = 0; i < 2; i++) {
#pragma unroll
        for (int rr = 0; rr < 2; rr++) {
            const int m  = m0 + wm + i * 16 + g + rr * 8;
            const int bb = m >> 11;
            const int ss = m & (Sv - 1);
#pragma unroll
            for (int j = 0; j < 8; j++) {
                float x0 = acc[i][j][rr * 2 + 0];
                float x1 = acc[i][j][rr * 2 + 1];
                const int n = n0 + wn + j * 8 + 2 * t;
                if (OUT == 1) {
                    *reinterpret_cast<float2*>(&Cf[(size_t)m * Hv + n]) =
                        make_float2(x0, x1);
                } else {
                    const int hh = n >> 6, dd = n & 63;
                    const size_t o = ((size_t)(bb * NHv + hh) * Sv + ss) * HDv + dd;
                    *reinterpret_cast<__half2*>(&C16[o]) =
                        __float22half2_rn(make_float2(x0, x1));
                }
            }
        }
    }
}

__global__ __launch_bounds__(256) void proj_v()
{
    extern __shared__ char smraw[];
    gemm2h_body<3>(g_ah16, g_al16, g_wv16, nullptr, g_v16,
                   (uint16_t*)smraw, blockIdx.y * 128, blockIdx.x * 128);
}

__global__ __launch_bounds__(256) void proj_o(float* __restrict__ out)
{
    extern __shared__ char smraw[];
    gemm2h_body<1>(g_aoh, g_aol, g_wo16, out, nullptr,
                   (uint16_t*)smraw, blockIdx.y * 128, blockIdx.x * 128);
}

// ---------------------------------------------------------------------------
// Flash attention: scores 3xBF16 via ldmatrix frags; PV 2-term FP16;
// cp.async double-buffered K/V/mask tiles; exp on MUFU. (round-10 exact form)
// ---------------------------------------------------------------------------
#define VPITCH 72
#define KVTILE (64 * 64 + 64 * 64 + 64 * VPITCH)    // 12800 halfs
#define OFF_KV (2 * 128 * 64)                       // 16384
#define OFF_END (OFF_KV + 2 * KVTILE)               // 41984 halfs
#define ATTN_SMEM (OFF_END * 2 + 2 * 64 * 4)        // 84480 B

__global__ __launch_bounds__(256, 2) void attn_mma(const int* __restrict__ mask)
{
    extern __shared__ char shraw[];
    uint16_t* Qh = (uint16_t*)shraw;
    uint16_t* Ql = Qh + 128 * 64;
    uint16_t* KV = Qh + OFF_KV;
    int* Msbase  = (int*)(Qh + OFF_END);

    const int bb = blockIdx.z;
    const int hh = blockIdx.y;
    const int q0 = blockIdx.x * 128;

    const size_t hb = (size_t)(bb * NHv + hh) * Sv;
    const __nv_bfloat16* Qhg = g_qhi + (hb + q0) * HDv;
    const __nv_bfloat16* Qlg = g_qlo + (hb + q0) * HDv;
    const __nv_bfloat16* Khg = g_khi + hb * HDv;
    const __nv_bfloat16* Klg = g_klo + hb * HDv;
    const __half*        Vg  = g_v16 + hb * HDv;

    const int tid  = threadIdx.x;
    const int w    = tid >> 5;
    const int lane = tid & 31;
    const int g    = lane >> 2;
    const int t    = lane & 3;
    const int qb   = w * 16;

    const int lrow8 = lane & 7;
    const int half8 = (lane >> 3) & 1;
    const int cbsel = lane >> 4;
    const int qrowL = qb + half8 * 8 + lrow8;
    const uint32_t qh_base = smem_u32(Qh);
    const uint32_t ql_base = smem_u32(Ql);
    const int ltile = lane >> 3;
    const int v_row_base = (ltile & 1) * 8 + lrow8;
    const int v_col_half = (ltile >> 1) * 8;

    // load Q tiles (hi/lo)
#pragma unroll
    for (int i = 0; i < 8; i++) {
        int idx = tid + i * 256;
        int row = idx >> 4, q4 = (idx & 15) * 4;
        int so = s64(row, q4);
        *reinterpret_cast<uint2*>(&Qh[so]) =
            *reinterpret_cast<const uint2*>(&Qhg[row * HDv + q4]);
        *reinterpret_cast<uint2*>(&Ql[so]) =
            *reinterpret_cast<const uint2*>(&Qlg[row * HDv + q4]);
    }

    auto prefetch = [&](int tt, int bbuf) {
        const int k0 = tt * 64;
        uint16_t* kv = KV + bbuf * KVTILE;
#pragma unroll
        for (int i = 0; i < 6; i++) {
            int idx = tid + i * 256;
            if (idx < 512) {
                int row = idx >> 3, seg = idx & 7;
                cp_async16(smem_u32(kv + row * 64 + ((seg ^ row) & 7) * 8),
                           Khg + (size_t)(k0 + row) * HDv + seg * 8);
            } else if (idx < 1024) {
                int rem = idx - 512;
                int row = rem >> 3, seg = rem & 7;
                cp_async16(smem_u32(kv + 4096 + row * 64 + ((seg ^ row) & 7) * 8),
                           Klg + (size_t)(k0 + row) * HDv + seg * 8);
            } else {
                int rem = idx - 1024;
                int row = rem >> 3, seg = rem & 7;
                cp_async16(smem_u32(kv + 8192 + row * VPITCH + seg * 8),
                           Vg + (size_t)(k0 + row) * HDv + seg * 8);
            }
        }
        if (tid < 16)
            cp_async16(smem_u32(Msbase + bbuf * 64 + tid * 4),
                       mask + bb * Sv + k0 + tid * 4);
    };

    float oacc[8][4];
#pragma unroll
    for (int j = 0; j < 8; j++)
#pragma unroll
        for (int r = 0; r < 4; r++) oacc[j][r] = 0.f;
    float m0r = -1e30f, m1r = -1e30f, l0r = 0.f, l1r = 0.f;

    prefetch(0, 0);
    CP_COMMIT();

    for (int tk = 0; tk < Sv / 64; tk++) {
        const int b = tk & 1;
        cp_wait<0>();
        __syncthreads();
        if (tk + 1 < Sv / 64) prefetch(tk + 1, b ^ 1);
        CP_COMMIT();

        const uint32_t khb = smem_u32(KV + b * KVTILE);
        const uint32_t klb = khb + 4096 * 2;
        const uint32_t vhb = khb + 8192 * 2;
        const int* Ms = Msbase + b * 64;

        // ---- scores (3xBF16, ldmatrix frags) ----
        float sacc[8][4];
#pragma unroll
        for (int j = 0; j < 8; j++)
#pragma unroll
            for (int r = 0; r < 4; r++) sacc[j][r] = 0.f;

#pragma unroll
        for (int kb = 0; kb < 4; kb++) {
            const int cb = kb * 2 + cbsel;
            const uint32_t qoff = (uint32_t)(qrowL * 64 + ((cb ^ qrowL) & 7) * 8) * 2;
            uint32_t ah[4], al[4];
            ldsm_x4(ah[0], ah[1], ah[2], ah[3], qh_base + qoff);
            ldsm_x4(al[0], al[1], al[2], al[3], ql_base + qoff);
#pragma unroll
            for (int p = 0; p < 4; p++) {
                const int krowL = p * 16 + half8 * 8 + lrow8;
                const uint32_t koff =
                    (uint32_t)(krowL * 64 + ((cb ^ krowL) & 7) * 8) * 2;
                uint32_t kh0, kh1, kh2, kh3, kl0, kl1, kl2, kl3;
                ldsm_x4(kh0, kh1, kh2, kh3, khb + koff);
                ldsm_x4(kl0, kl1, kl2, kl3, klb + koff);
                mma16(sacc[2 * p],     ah, kl0, kl2);
                mma16(sacc[2 * p],     al, kh0, kh2);
                mma16(sacc[2 * p],     ah, kh0, kh2);
                mma16(sacc[2 * p + 1], ah, kl1, kl3);
                mma16(sacc[2 * p + 1], al, kh1, kh3);
                mma16(sacc[2 * p + 1], ah, kh1, kh3);
            }
        }

        // ---- mask ----
#pragma unroll
        for (int j = 0; j < 8; j++) {
            if (Ms[j * 8 + 2 * t] == 0)     { sacc[j][0] = -1e30f; sacc[j][2] = -1e30f; }
            if (Ms[j * 8 + 2 * t + 1] == 0) { sacc[j][1] = -1e30f; sacc[j][3] = -1e30f; }
        }

        // ---- online softmax (exp on MUFU) ----
        float mx0 = -1e30f, mx1 = -1e30f;
#pragma unroll
        for (int j = 0; j < 8; j++) {
            mx0 = fmaxf(mx0, fmaxf(sacc[j][0], sacc[j][1]));
            mx1 = fmaxf(mx1, fmaxf(sacc[j][2], sacc[j][3]));
        }
        mx0 = fmaxf(mx0, __shfl_xor_sync(0xffffffffu, mx0, 1));
        mx0 = fmaxf(mx0, __shfl_xor_sync(0xffffffffu, mx0, 2));
        mx1 = fmaxf(mx1, __shfl_xor_sync(0xffffffffu, mx1, 1));
        mx1 = fmaxf(mx1, __shfl_xor_sync(0xffffffffu, mx1, 2));

        const float mn0 = fmaxf(m0r, mx0);
        const float mn1 = fmaxf(m1r, mx1);
        const float a0  = __expf(m0r - mn0);
        const float a1  = __expf(m1r - mn1);
        m0r = mn0; m1r = mn1;

        float s0 = 0.f, s1 = 0.f;
#pragma unroll
        for (int j = 0; j < 8; j++) {
            sacc[j][0] = __expf(sacc[j][0] - mn0);
            sacc[j][1] = __expf(sacc[j][1] - mn0);
            sacc[j][2] = __expf(sacc[j][2] - mn1);
            sacc[j][3] = __expf(sacc[j][3] - mn1);
            s0 += sacc[j][0] + sacc[j][1];
            s1 += sacc[j][2] + sacc[j][3];
        }
        s0 += __shfl_xor_sync(0xffffffffu, s0, 1);
        s0 += __shfl_xor_sync(0xffffffffu, s0, 2);
        s1 += __shfl_xor_sync(0xffffffffu, s1, 1);
        s1 += __shfl_xor_sync(0xffffffffu, s1, 2);
        l0r = l0r * a0 + s0;
        l1r = l1r * a1 + s1;
#pragma unroll
        for (int j = 0; j < 8; j++) {
            oacc[j][0] *= a0; oacc[j][1] *= a0;
            oacc[j][2] *= a1; oacc[j][3] *= a1;
        }

        // ---- O += P @ V  (2-term FP16) ----
#pragma unroll
        for (int jp2 = 0; jp2 < 4; jp2++) {
            uint32_t ap_h[4], ap_l[4];
#pragma unroll
            for (int half = 0; half < 2; half++) {
                const float* c = sacc[2 * jp2 + half];
                __half2 h01 = __float22half2_rn(make_float2(c[0], c[1]));
                __half2 h23 = __float22half2_rn(make_float2(c[2], c[3]));
                float2 f01 = __half22float2(h01);
                float2 f23 = __half22float2(h23);
                __half2 l01 = __float22half2_rn(make_float2(c[0] - f01.x, c[1] - f01.y));
                __half2 l23 = __float22half2_rn(make_float2(c[2] - f23.x, c[3] - f23.y));
                ap_h[half == 0 ? 0 : 2] = *reinterpret_cast<uint32_t*>(&h01);
                ap_h[half == 0 ? 1 : 3] = *reinterpret_cast<uint32_t*>(&h23);
                ap_l[half == 0 ? 0 : 2] = *reinterpret_cast<uint32_t*>(&l01);
                ap_l[half == 0 ? 1 : 3] = *reinterpret_cast<uint32_t*>(&l23);
            }
            const uint32_t vrow =
                (uint32_t)((jp2 * 16 + v_row_base) * VPITCH * 2 + v_col_half * 2);
#pragma unroll
            for (int jp = 0; jp < 4; jp++) {
                uint32_t b0, b1, b2, b3;
                ldsm_x4_trans(b0, b1, b2, b3, vhb + vrow + jp * 32);
                mma16h(oacc[jp * 2 + 0], ap_l, b0, b1);
                mma16h(oacc[jp * 2 + 0], ap_h, b0, b1);
                mma16h(oacc[jp * 2 + 1], ap_l, b2, b3);
                mma16h(oacc[jp * 2 + 1], ap_h, b2, b3);
            }
        }
    }

    // ---- normalize + split-write fp16 hi/lo planes [B,S,H] ----
    const float i0 = 1.f / l0r;
    const float i1 = 1.f / l1r;
    const int r0 = q0 + qb + g;
    const int r1 = r0 + 8;
#pragma unroll
    for (int j = 0; j < 8; j++) {
        const int col = hh * 64 + j * 8 + 2 * t;
        float y0 = oacc[j][0] * i0, y1 = oacc[j][1] * i0;
        float y2 = oacc[j][2] * i1, y3 = oacc[j][3] * i1;
        __half2 H0 = __float22half2_rn(make_float2(y0, y1));
        float2 F0 = __half22float2(H0);
        __half2 L0 = __float22half2_rn(make_float2(y0 - F0.x, y1 - F0.y));
        __half2 H1 = __float22half2_rn(make_float2(y2, y3));
        float2 F1 = __half22float2(H1);
        __half2 L1 = __float22half2_rn(make_float2(y2 - F1.x, y3 - F1.y));
        const size_t o0 = ((size_t)bb * Sv + r0) * Hv + col;
        const size_t o1 = ((size_t)bb * Sv + r1) * Hv + col;
        *reinterpret_cast<__half2*>(&g_aoh[o0]) = H0;
        *reinterpret_cast<__half2*>(&g_aol[o0]) = L0;
        *reinterpret_cast<__half2*>(&g_aoh[o1]) = H1;
        *reinterpret_cast<__half2*>(&g_aol[o1]) = L1;
    }
}

// ---------------------------------------------------------------------------
extern "C" void kernel_launch(void* const* d_in, const int* in_sizes, int n_in,
                              void* d_out, int out_size)
{
    const float* hs   = (const float*)d_in[0];
    const int*   mask = (const int*)d_in[1];
    const float* Wq   = (const float*)d_in[2];
    const float* Wk   = (const float*)d_in[3];
    const float* Wv   = (const float*)d_in[4];
    const float* Wo   = (const float*)d_in[5];
    float*       out  = (float*)d_out;

    cudaFuncSetAttribute(proj_qk, cudaFuncAttributeMaxDynamicSharedMemorySize, QK_SMEM);
    cudaFuncSetAttribute(proj_v,  cudaFuncAttributeMaxDynamicSharedMemorySize, GEMM_O_SMEM);
    cudaFuncSetAttribute(proj_o,  cudaFuncAttributeMaxDynamicSharedMemorySize, GEMM_O_SMEM);
    cudaFuncSetAttribute(attn_mma, cudaFuncAttributeMaxDynamicSharedMemorySize, ATTN_SMEM);

    split_hidden<<<Mv * Hv / 1024, 256>>>(hs);
    split_wqk<<<dim3(Hv * Hv / 1024, 1, 2), 256>>>(Wq, Wk);
    cvt_wvo<<<dim3(Hv * Hv / 1024, 1, 2), 256>>>(Wv, Wo);

    proj_qk<<<dim3(Hv / 64, Mv / 128, 2), 256, QK_SMEM>>>();
    proj_v<<<dim3(Hv / 128, Mv / 128), 256, GEMM_O_SMEM>>>();

    attn_mma<<<dim3(Sv / 128, NHv, Bv), 256, ATTN_SMEM>>>(mask);

    proj_o<<<dim3(Hv / 128, Mv / 128), 256, GEMM_O_SMEM>>>(out);
}

// round 13
// speedup vs baseline: 1.1635x; 1.0691x over previous
#include <cuda_runtime.h>
#include <cuda_bf16.h>
#include <cuda_fp16.h>
#include <cstdint>

// Problem constants
#define Bv   2
#define Sv   2048
#define Hv   1024
#define NHv  16
#define HDv  64
#define Mv   (Bv * Sv)

// Scratch (device globals — no allocation allowed)
__device__ __nv_bfloat16 g_ahi[Mv * Hv], g_alo[Mv * Hv];
__device__ __half        g_ah16[Mv * Hv], g_al16[Mv * Hv];
__device__ __nv_bfloat16 g_wqhi[Hv * Hv], g_wqlo[Hv * Hv];
__device__ __nv_bfloat16 g_wkhi[Hv * Hv], g_wklo[Hv * Hv];
__device__ __half        g_wv16[Hv * Hv];
__device__ __half        g_wo16[Hv * Hv];
__device__ __nv_bfloat16 g_qhi[Mv * Hv], g_qlo[Mv * Hv];
__device__ __nv_bfloat16 g_khi[Mv * Hv], g_klo[Mv * Hv];
__device__ __half        g_v16[Mv * Hv];
__device__ __half        g_aoh[Mv * Hv], g_aol[Mv * Hv];

__device__ __forceinline__ float elu1(float x) {
    return x > 0.f ? x + 1.f : __expf(x);
}

// ---------------------------------------------------------------------------
// helpers
// ---------------------------------------------------------------------------
__device__ __forceinline__ void splitb(float x, __nv_bfloat16& h, __nv_bfloat16& l) {
    h = __float2bfloat16(x);
    l = __float2bfloat16(x - __bfloat162float(h));
}
__device__ __forceinline__ void mma16(float* c, const uint32_t* a, uint32_t b0, uint32_t b1) {
    asm volatile(
        "mma.sync.aligned.m16n8k16.row.col.f32.bf16.bf16.f32 "
        "{%0,%1,%2,%3}, {%4,%5,%6,%7}, {%8,%9}, {%0,%1,%2,%3};"
        : "+f"(c[0]), "+f"(c[1]), "+f"(c[2]), "+f"(c[3])
        : "r"(a[0]), "r"(a[1]), "r"(a[2]), "r"(a[3]), "r"(b0), "r"(b1));
}
__device__ __forceinline__ void mma16h(float* c, const uint32_t* a, uint32_t b0, uint32_t b1) {
    asm volatile(
        "mma.sync.aligned.m16n8k16.row.col.f32.f16.f16.f32 "
        "{%0,%1,%2,%3}, {%4,%5,%6,%7}, {%8,%9}, {%0,%1,%2,%3};"
        : "+f"(c[0]), "+f"(c[1]), "+f"(c[2]), "+f"(c[3])
        : "r"(a[0]), "r"(a[1]), "r"(a[2]), "r"(a[3]), "r"(b0), "r"(b1));
}
__device__ __forceinline__ void ldsm_x4(uint32_t& r0, uint32_t& r1,
                                        uint32_t& r2, uint32_t& r3, uint32_t addr) {
    asm volatile("ldmatrix.sync.aligned.m8n8.x4.shared.b16 {%0,%1,%2,%3}, [%4];"
        : "=r"(r0), "=r"(r1), "=r"(r2), "=r"(r3) : "r"(addr));
}
__device__ __forceinline__ void ldsm_x4_trans(uint32_t& r0, uint32_t& r1,
                                              uint32_t& r2, uint32_t& r3, uint32_t addr) {
    asm volatile("ldmatrix.sync.aligned.m8n8.x4.trans.shared.b16 {%0,%1,%2,%3}, [%4];"
        : "=r"(r0), "=r"(r1), "=r"(r2), "=r"(r3) : "r"(addr));
}
__device__ __forceinline__ uint32_t smem_u32(const void* p) {
    uint32_t a;
    asm("{ .reg .u64 t; cvta.to.shared.u64 t, %1; cvt.u32.u64 %0, t; }" : "=r"(a) : "l"(p));
    return a;
}
__device__ __forceinline__ void cp_async16(uint32_t sm, const void* g) {
    asm volatile("cp.async.cg.shared.global [%0], [%1], 16;" :: "r"(sm), "l"(g));
}
#define CP_COMMIT() asm volatile("cp.async.commit_group;" ::: "memory")
template <int N>
__device__ __forceinline__ void cp_wait() {
    asm volatile("cp.async.wait_group %0;" :: "n"(N) : "memory");
}

// smem swizzles (16B-block XOR by row)
__device__ __forceinline__ int sxh(int row, int col) {     // 32-half rows (proj tiles)
    return row * 32 + ((col & 7) | ((((col >> 3) ^ (row >> 1)) & 3) << 3));
}
__device__ __forceinline__ int s64(int row, int col) {     // 64-half rows (attn Q/K)
    return row * 64 + ((col & 7) | ((((col >> 3) ^ row) & 7) << 3));
}
// byte offset of the 16B segment holding (row, colblock cb) in a 32-half-row tile
__device__ __forceinline__ uint32_t sxh_seg(int row, int cb) {
    return (uint32_t)((row * 32 + ((cb ^ (row >> 1)) & 3) * 8) * 2);
}

// ---------------------------------------------------------------------------
// Prep kernels (fused)
// ---------------------------------------------------------------------------
__global__ void split_hidden(const float* __restrict__ src)
{
    int i = (blockIdx.x * 256 + threadIdx.x) * 4;
    float4 x = *reinterpret_cast<const float4*>(src + i);
    __nv_bfloat16 bh[4], bl[4];
    splitb(x.x, bh[0], bl[0]); splitb(x.y, bh[1], bl[1]);
    splitb(x.z, bh[2], bl[2]); splitb(x.w, bh[3], bl[3]);
    __nv_bfloat162 BH0; BH0.x = bh[0]; BH0.y = bh[1];
    __nv_bfloat162 BH1; BH1.x = bh[2]; BH1.y = bh[3];
    __nv_bfloat162 BL0; BL0.x = bl[0]; BL0.y = bl[1];
    __nv_bfloat162 BL1; BL1.x = bl[2]; BL1.y = bl[3];
    *reinterpret_cast<__nv_bfloat162*>(g_ahi + i)     = BH0;
    *reinterpret_cast<__nv_bfloat162*>(g_ahi + i + 2) = BH1;
    *reinterpret_cast<__nv_bfloat162*>(g_alo + i)     = BL0;
    *reinterpret_cast<__nv_bfloat162*>(g_alo + i + 2) = BL1;
    __half hh[4], hl[4];
    hh[0] = __float2half_rn(x.x); hh[1] = __float2half_rn(x.y);
    hh[2] = __float2half_rn(x.z); hh[3] = __float2half_rn(x.w);
    hl[0] = __float2half_rn(x.x - __half2float(hh[0]));
    hl[1] = __float2half_rn(x.y - __half2float(hh[1]));
    hl[2] = __float2half_rn(x.z - __half2float(hh[2]));
    hl[3] = __float2half_rn(x.w - __half2float(hh[3]));
    __half2 HH0; HH0.x = hh[0]; HH0.y = hh[1];
    __half2 HH1; HH1.x = hh[2]; HH1.y = hh[3];
    __half2 HL0; HL0.x = hl[0]; HL0.y = hl[1];
    __half2 HL1; HL1.x = hl[2]; HL1.y = hl[3];
    *reinterpret_cast<__half2*>(g_ah16 + i)     = HH0;
    *reinterpret_cast<__half2*>(g_ah16 + i + 2) = HH1;
    *reinterpret_cast<__half2*>(g_al16 + i)     = HL0;
    *reinterpret_cast<__half2*>(g_al16 + i + 2) = HL1;
}

__global__ void split_wqk(const float* __restrict__ Wq, const float* __restrict__ Wk)
{
    const float* src = blockIdx.z ? Wk : Wq;
    __nv_bfloat16* hi = blockIdx.z ? g_wkhi : g_wqhi;
    __nv_bfloat16* lo = blockIdx.z ? g_wklo : g_wqlo;
    int i = (blockIdx.x * 256 + threadIdx.x) * 4;
    float4 x = *reinterpret_cast<const float4*>(src + i);
    __nv_bfloat16 h[4], l[4];
    splitb(x.x, h[0], l[0]); splitb(x.y, h[1], l[1]);
    splitb(x.z, h[2], l[2]); splitb(x.w, h[3], l[3]);
    __nv_bfloat162 H0; H0.x = h[0]; H0.y = h[1];
    __nv_bfloat162 H1; H1.x = h[2]; H1.y = h[3];
    __nv_bfloat162 L0; L0.x = l[0]; L0.y = l[1];
    __nv_bfloat162 L1; L1.x = l[2]; L1.y = l[3];
    *reinterpret_cast<__nv_bfloat162*>(hi + i)     = H0;
    *reinterpret_cast<__nv_bfloat162*>(hi + i + 2) = H1;
    *reinterpret_cast<__nv_bfloat162*>(lo + i)     = L0;
    *reinterpret_cast<__nv_bfloat162*>(lo + i + 2) = L1;
}

__global__ void cvt_wvo(const float* __restrict__ Wv, const float* __restrict__ Wo)
{
    const float* src = blockIdx.z ? Wo : Wv;
    __half*      dst = blockIdx.z ? g_wo16 : g_wv16;
    int i = (blockIdx.x * 256 + threadIdx.x) * 4;
    float4 x = *reinterpret_cast<const float4*>(src + i);
    *reinterpret_cast<__half2*>(dst + i)     = __float22half2_rn(make_float2(x.x, x.y));
    *reinterpret_cast<__half2*>(dst + i + 2) = __float22half2_rn(make_float2(x.z, x.w));
}

// ---------------------------------------------------------------------------
// 3xBF16 GEMM (Q/K projections): tile 128x64, warp 32x32, ldmatrix fragments.
// ---------------------------------------------------------------------------
#define BK 32
#define NKC (Hv / BK)
#define QK_STG_H (2 * 128 * 32 + 2 * 64 * 32)
#define QK_SMEM (3 * QK_STG_H * 2)

__global__ __launch_bounds__(256, 2) void proj_qk()
{
    extern __shared__ char smraw[];
    uint16_t* sm = (uint16_t*)smraw;
    const int z  = blockIdx.z;
    const __nv_bfloat16* Ah = g_ahi;
    const __nv_bfloat16* Al = g_alo;
    const __nv_bfloat16* Bh = z == 0 ? g_wqhi : g_wkhi;
    const __nv_bfloat16* Bl = z == 0 ? g_wqlo : g_wklo;
    __nv_bfloat16* Chi = z == 0 ? g_qhi : g_khi;
    __nv_bfloat16* Clo = z == 0 ? g_qlo : g_klo;
    const int m0 = blockIdx.y * 128, n0 = blockIdx.x * 64;

    const int tid  = threadIdx.x;
    const int w    = tid >> 5;
    const int lane = tid & 31;
    const int g    = lane >> 2;
    const int t    = lane & 3;
    const int wm   = (w & 3) * 32;
    const int wn   = (w >> 2) * 32;

    // ldmatrix per-lane geometry
    const int rA0   = wm + (lane & 15);            // A rows, i=0 (i=1: +16)
    const int colsA = lane >> 4;                   // 0/1: k col-block select
    const int rB0   = wn + ((lane >> 4) & 1) * 8 + (lane & 7);  // B rows, pair 0 (pair1: +16)
    const int bselB = (lane >> 3) & 1;             // k col-block select for B

    auto load_stage = [&](int c, int s) {
        const int k0 = c * BK;
        uint16_t* st = sm + s * QK_STG_H;
#pragma unroll
        for (int i = 0; i < 6; i++) {
            int idx = tid + i * 256;
            const __nv_bfloat16* gp;
            int row, seg, base;
            if (idx < 512)        { row = idx >> 2;          seg = idx & 3;
                                    gp = Ah + (size_t)(m0 + row) * Hv; base = 0; }
            else if (idx < 1024)  { int r2 = idx - 512;  row = r2 >> 2; seg = r2 & 3;
                                    gp = Al + (size_t)(m0 + row) * Hv; base = 4096; }
            else if (idx < 1280)  { int r2 = idx - 1024; row = r2 >> 2; seg = r2 & 3;
                                    gp = Bh + (size_t)(n0 + row) * Hv; base = 8192; }
            else                  { int r2 = idx - 1280; row = r2 >> 2; seg = r2 & 3;
                                    gp = Bl + (size_t)(n0 + row) * Hv; base = 10240; }
            int sc = ((seg ^ (row >> 1)) & 3) * 8;
            cp_async16(smem_u32(st + base + row * 32 + sc), gp + k0 + seg * 8);
        }
    };

    float acc[2][4][4];
#pragma unroll
    for (int i = 0; i < 2; i++)
#pragma unroll
        for (int j = 0; j < 4; j++)
#pragma unroll
            for (int r = 0; r < 4; r++) acc[i][j][r] = 0.f;

    load_stage(0, 0); CP_COMMIT();
    load_stage(1, 1); CP_COMMIT();

    for (int c = 0; c < NKC; c++) {
        cp_wait<1>();
        __syncthreads();
        if (c + 2 < NKC) load_stage(c + 2, (c + 2) % 3);
        CP_COMMIT();

        const uint32_t stb  = smem_u32(sm + (c % 3) * QK_STG_H);
        const uint32_t sAhb = stb;
        const uint32_t sAlb = stb + 8192;
        const uint32_t sBhb = stb + 16384;
        const uint32_t sBlb = stb + 20480;

#pragma unroll
        for (int kb = 0; kb < 2; kb++) {
            const int cbA = kb * 2 + colsA;
            const int cbB = kb * 2 + bselB;
            const uint32_t oA0 = sxh_seg(rA0,      cbA);
            const uint32_t oA1 = sxh_seg(rA0 + 16, cbA);
            const uint32_t oB0 = sxh_seg(rB0,      cbB);
            const uint32_t oB1 = sxh_seg(rB0 + 16, cbB);

            uint32_t ah[2][4], al[2][4];
            ldsm_x4(ah[0][0], ah[0][1], ah[0][2], ah[0][3], sAhb + oA0);
            ldsm_x4(ah[1][0], ah[1][1], ah[1][2], ah[1][3], sAhb + oA1);
            ldsm_x4(al[0][0], al[0][1], al[0][2], al[0][3], sAlb + oA0);
            ldsm_x4(al[1][0], al[1][1], al[1][2], al[1][3], sAlb + oA1);

            uint32_t bh[4][2], bl[4][2];
            ldsm_x4(bh[0][0], bh[0][1], bh[1][0], bh[1][1], sBhb + oB0);
            ldsm_x4(bh[2][0], bh[2][1], bh[3][0], bh[3][1], sBhb + oB1);
            ldsm_x4(bl[0][0], bl[0][1], bl[1][0], bl[1][1], sBlb + oB0);
            ldsm_x4(bl[2][0], bl[2][1], bl[3][0], bl[3][1], sBlb + oB1);

#pragma unroll
            for (int j = 0; j < 4; j++) {
#pragma unroll
                for (int i = 0; i < 2; i++) {
                    mma16(acc[i][j], ah[i], bl[j][0], bl[j][1]);
                    mma16(acc[i][j], al[i], bh[j][0], bh[j][1]);
                    mma16(acc[i][j], ah[i], bh[j][0], bh[j][1]);
                }
            }
        }
    }

#pragma unroll
    for (int i = 0; i < 2; i++) {
#pragma unroll
        for (int rr = 0; rr < 2; rr++) {
            const int m  = m0 + wm + i * 16 + g + rr * 8;
            const int bb = m >> 11;
            const int ss = m & (Sv - 1);
#pragma unroll
            for (int j = 0; j < 4; j++) {
                float x0 = elu1(acc[i][j][rr * 2 + 0]);
                float x1 = elu1(acc[i][j][rr * 2 + 1]);
                const int n = n0 + wn + j * 8 + 2 * t;
                const int hh = n >> 6, dd = n & 63;
                const size_t o = ((size_t)(bb * NHv + hh) * Sv + ss) * HDv + dd;
                __nv_bfloat16 h0, l0, h1, l1;
                splitb(x0, h0, l0);
                splitb(x1, h1, l1);
                __nv_bfloat162 H; H.x = h0; H.y = h1;
                __nv_bfloat162 L; L.x = l0; L.y = l1;
                *reinterpret_cast<__nv_bfloat162*>(&Chi[o]) = H;
                *reinterpret_cast<__nv_bfloat162*>(&Clo[o]) = L;
            }
        }
    }
}

// ---------------------------------------------------------------------------
// 2-term FP16 GEMM: C = (Ah + Al) @ W16^T.  ldmatrix fragments.
// OUT 1: fp32 [M,N] row-major;  OUT 3: fp16 plane [B,NH,S,HD] (V)
// ---------------------------------------------------------------------------
#define STG_O (3 * 128 * 32)
#define GEMM_O_SMEM (3 * STG_O * 2)

template <int OUT>
__device__ __forceinline__ void gemm2h_body(
    const __half* __restrict__ Ah, const __half* __restrict__ Al,
    const __half* __restrict__ W16,
    float* __restrict__ Cf, __half* __restrict__ C16,
    uint16_t* sm, int m0, int n0)
{
    const int tid  = threadIdx.x;
    const int w    = tid >> 5;
    const int lane = tid & 31;
    const int g    = lane >> 2;
    const int t    = lane & 3;
    const int wm   = (w & 3) * 32;
    const int wn   = (w >> 2) * 64;

    const int rA0   = wm + (lane & 15);
    const int colsA = lane >> 4;
    const int rW0   = wn + ((lane >> 4) & 1) * 8 + (lane & 7);   // pairs: +16p
    const int bselW = (lane >> 3) & 1;

    auto load_stage = [&](int c, int s) {
        const int k0 = c * BK;
        uint16_t* st = sm + s * STG_O;
#pragma unroll
        for (int i = 0; i < 6; i++) {
            int idx = tid + i * 256;
            int arr = idx >> 9;
            int rem = idx & 511;
            int row = rem >> 2, seg = rem & 3;
            const __half* gp;
            if (arr == 0)      gp = Ah  + (size_t)(m0 + row) * Hv;
            else if (arr == 1) gp = Al  + (size_t)(m0 + row) * Hv;
            else               gp = W16 + (size_t)(n0 + row) * Hv;
            int sc = ((seg ^ (row >> 1)) & 3) * 8;
            cp_async16(smem_u32(st + arr * 4096 + row * 32 + sc), gp + k0 + seg * 8);
        }
    };

    float acc[2][8][4];
#pragma unroll
    for (int i = 0; i < 2; i++)
#pragma unroll
        for (int j = 0; j < 8; j++)
#pragma unroll
            for (int r = 0; r < 4; r++) acc[i][j][r] = 0.f;

    load_stage(0, 0); CP_COMMIT();
    load_stage(1, 1); CP_COMMIT();

    for (int c = 0; c < NKC; c++) {
        cp_wait<1>();
        __syncthreads();
        if (c + 2 < NKC) load_stage(c + 2, (c + 2) % 3);
        CP_COMMIT();

        const uint32_t stb  = smem_u32(sm + (c % 3) * STG_O);
        const uint32_t sAhb = stb;
        const uint32_t sAlb = stb + 8192;
        const uint32_t sWb  = stb + 16384;

#pragma unroll
        for (int kb = 0; kb < 2; kb++) {
            const int cbA = kb * 2 + colsA;
            const int cbW = kb * 2 + bselW;
            const uint32_t oA0 = sxh_seg(rA0,      cbA);
            const uint32_t oA1 = sxh_seg(rA0 + 16, cbA);

            uint32_t ah[2][4], al[2][4];
            ldsm_x4(ah[0][0], ah[0][1], ah[0][2], ah[0][3], sAhb + oA0);
            ldsm_x4(ah[1][0], ah[1][1], ah[1][2], ah[1][3], sAhb + oA1);
            ldsm_x4(al[0][0], al[0][1], al[0][2], al[0][3], sAlb + oA0);
            ldsm_x4(al[1][0], al[1][1], al[1][2], al[1][3], sAlb + oA1);

            uint32_t bw[8][2];
#pragma unroll
            for (int p = 0; p < 4; p++) {
                const uint32_t oW = sxh_seg(rW0 + p * 16, cbW);
                ldsm_x4(bw[2 * p][0], bw[2 * p][1], bw[2 * p + 1][0], bw[2 * p + 1][1],
                        sWb + oW);
            }
#pragma unroll
            for (int j = 0; j < 8; j++) {
#pragma unroll
                for (int i = 0; i < 2; i++) {
                    mma16h(acc[i][j], al[i], bw[j][0], bw[j][1]);
                    mma16h(acc[i][j], ah[i], bw[j][0], bw[j][1]);
                }
            }
        }
    }

#pragma unroll
    for (int i = 0; i < 2; i++) {
#pragma unroll
        for (int rr = 0; rr < 2; rr++) {
            const int m  = m0 + wm + i * 16 + g + rr * 8;
            const int bb = m >> 11;
            const int ss = m & (Sv - 1);
#pragma unroll
            for (int j = 0; j < 8; j++) {
                float x0 = acc[i][j][rr * 2 + 0];
                float x1 = acc[i][j][rr * 2 + 1];
                const int n = n0 + wn + j * 8 + 2 * t;
                if (OUT == 1) {
                    *reinterpret_cast<float2*>(&Cf[(size_t)m * Hv + n]) =
                        make_float2(x0, x1);
                } else {
                    const int hh = n >> 6, dd = n & 63;
                    const size_t o = ((size_t)(bb * NHv + hh) * Sv + ss) * HDv + dd;
                    *reinterpret_cast<__half2*>(&C16[o]) =
                        __float22half2_rn(make_float2(x0, x1));
                }
            }
        }
    }
}

__global__ __launch_bounds__(256) void proj_v()
{
    extern __shared__ char smraw[];
    gemm2h_body<3>(g_ah16, g_al16, g_wv16, nullptr, g_v16,
                   (uint16_t*)smraw, blockIdx.y * 128, blockIdx.x * 128);
}

__global__ __launch_bounds__(256) void proj_o(float* __restrict__ out)
{
    extern __shared__ char smraw[];
    gemm2h_body<1>(g_aoh, g_aol, g_wo16, out, nullptr,
                   (uint16_t*)smraw, blockIdx.y * 128, blockIdx.x * 128);
}

// ---------------------------------------------------------------------------
// Flash attention (round-12 exact form — untouched)
// ---------------------------------------------------------------------------
#define VPITCH 72
#define KVTILE (64 * 64 + 64 * 64 + 64 * VPITCH)
#define OFF_KV (2 * 128 * 64)
#define OFF_END (OFF_KV + 2 * KVTILE)
#define ATTN_SMEM (OFF_END * 2 + 2 * 64 * 4)

__global__ __launch_bounds__(256, 2) void attn_mma(const int* __restrict__ mask)
{
    extern __shared__ char shraw[];
    uint16_t* Qh = (uint16_t*)shraw;
    uint16_t* Ql = Qh + 128 * 64;
    uint16_t* KV = Qh + OFF_KV;
    int* Msbase  = (int*)(Qh + OFF_END);

    const int bb = blockIdx.z;
    const int hh = blockIdx.y;
    const int q0 = blockIdx.x * 128;

    const size_t hb = (size_t)(bb * NHv + hh) * Sv;
    const __nv_bfloat16* Qhg = g_qhi + (hb + q0) * HDv;
    const __nv_bfloat16* Qlg = g_qlo + (hb + q0) * HDv;
    const __nv_bfloat16* Khg = g_khi + hb * HDv;
    const __nv_bfloat16* Klg = g_klo + hb * HDv;
    const __half*        Vg  = g_v16 + hb * HDv;

    const int tid  = threadIdx.x;
    const int w    = tid >> 5;
    const int lane = tid & 31;
    const int g    = lane >> 2;
    const int t    = lane & 3;
    const int qb   = w * 16;

    const int lrow8 = lane & 7;
    const int half8 = (lane >> 3) & 1;
    const int cbsel = lane >> 4;
    const int qrowL = qb + half8 * 8 + lrow8;
    const uint32_t qh_base = smem_u32(Qh);
    const uint32_t ql_base = smem_u32(Ql);
    const int ltile = lane >> 3;
    const int v_row_base = (ltile & 1) * 8 + lrow8;
    const int v_col_half = (ltile >> 1) * 8;

#pragma unroll
    for (int i = 0; i < 8; i++) {
        int idx = tid + i * 256;
        int row = idx >> 4, q4 = (idx & 15) * 4;
        int so = s64(row, q4);
        *reinterpret_cast<uint2*>(&Qh[so]) =
            *reinterpret_cast<const uint2*>(&Qhg[row * HDv + q4]);
        *reinterpret_cast<uint2*>(&Ql[so]) =
            *reinterpret_cast<const uint2*>(&Qlg[row * HDv + q4]);
    }

    auto prefetch = [&](int tt, int bbuf) {
        const int k0 = tt * 64;
        uint16_t* kv = KV + bbuf * KVTILE;
#pragma unroll
        for (int i = 0; i < 6; i++) {
            int idx = tid + i * 256;
            if (idx < 512) {
                int row = idx >> 3, seg = idx & 7;
                cp_async16(smem_u32(kv + row * 64 + ((seg ^ row) & 7) * 8),
                           Khg + (size_t)(k0 + row) * HDv + seg * 8);
            } else if (idx < 1024) {
                int rem = idx - 512;
                int row = rem >> 3, seg = rem & 7;
                cp_async16(smem_u32(kv + 4096 + row * 64 + ((seg ^ row) & 7) * 8),
                           Klg + (size_t)(k0 + row) * HDv + seg * 8);
            } else {
                int rem = idx - 1024;
                int row = rem >> 3, seg = rem & 7;
                cp_async16(smem_u32(kv + 8192 + row * VPITCH + seg * 8),
                           Vg + (size_t)(k0 + row) * HDv + seg * 8);
            }
        }
        if (tid < 16)
            cp_async16(smem_u32(Msbase + bbuf * 64 + tid * 4),
                       mask + bb * Sv + k0 + tid * 4);
    };

    float oacc[8][4];
#pragma unroll
    for (int j = 0; j < 8; j++)
#pragma unroll
        for (int r = 0; r < 4; r++) oacc[j][r] = 0.f;
    float m0r = -1e30f, m1r = -1e30f, l0r = 0.f, l1r = 0.f;

    prefetch(0, 0);
    CP_COMMIT();

    for (int tk = 0; tk < Sv / 64; tk++) {
        const int b = tk & 1;
        cp_wait<0>();
        __syncthreads();
        if (tk + 1 < Sv / 64) prefetch(tk + 1, b ^ 1);
        CP_COMMIT();

        const uint32_t khb = smem_u32(KV + b * KVTILE);
        const uint32_t klb = khb + 4096 * 2;
        const uint32_t vhb = khb + 8192 * 2;
        const int* Ms = Msbase + b * 64;

        float sacc[8][4];
#pragma unroll
        for (int j = 0; j < 8; j++)
#pragma unroll
            for (int r = 0; r < 4; r++) sacc[j][r] = 0.f;

#pragma unroll
        for (int kb = 0; kb < 4; kb++) {
            const int cb = kb * 2 + cbsel;
            const uint32_t qoff = (uint32_t)(qrowL * 64 + ((cb ^ qrowL) & 7) * 8) * 2;
            uint32_t ah[4], al[4];
            ldsm_x4(ah[0], ah[1], ah[2], ah[3], qh_base + qoff);
            ldsm_x4(al[0], al[1], al[2], al[3], ql_base + qoff);
#pragma unroll
            for (int p = 0; p < 4; p++) {
                const int krowL = p * 16 + half8 * 8 + lrow8;
                const uint32_t koff =
                    (uint32_t)(krowL * 64 + ((cb ^ krowL) & 7) * 8) * 2;
                uint32_t kh0, kh1, kh2, kh3, kl0, kl1, kl2, kl3;
                ldsm_x4(kh0, kh1, kh2, kh3, khb + koff);
                ldsm_x4(kl0, kl1, kl2, kl3, klb + koff);
                mma16(sacc[2 * p],     ah, kl0, kl2);
                mma16(sacc[2 * p],     al, kh0, kh2);
                mma16(sacc[2 * p],     ah, kh0, kh2);
                mma16(sacc[2 * p + 1], ah, kl1, kl3);
                mma16(sacc[2 * p + 1], al, kh1, kh3);
                mma16(sacc[2 * p + 1], ah, kh1, kh3);
            }
        }

#pragma unroll
        for (int j = 0; j < 8; j++) {
            if (Ms[j * 8 + 2 * t] == 0)     { sacc[j][0] = -1e30f; sacc[j][2] = -1e30f; }
            if (Ms[j * 8 + 2 * t + 1] == 0) { sacc[j][1] = -1e30f; sacc[j][3] = -1e30f; }
        }

        float mx0 = -1e30f, mx1 = -1e30f;
#pragma unroll
        for (int j = 0; j < 8; j++) {
            mx0 = fmaxf(mx0, fmaxf(sacc[j][0], sacc[j][1]));
            mx1 = fmaxf(mx1, fmaxf(sacc[j][2], sacc[j][3]));
        }
        mx0 = fmaxf(mx0, __shfl_xor_sync(0xffffffffu, mx0, 1));
        mx0 = fmaxf(mx0, __shfl_xor_sync(0xffffffffu, mx0, 2));
        mx1 = fmaxf(mx1, __shfl_xor_sync(0xffffffffu, mx1, 1));
        mx1 = fmaxf(mx1, __shfl_xor_sync(0xffffffffu, mx1, 2));

        const float mn0 = fmaxf(m0r, mx0);
        const float mn1 = fmaxf(m1r, mx1);
        const float a0  = __expf(m0r - mn0);
        const float a1  = __expf(m1r - mn1);
        m0r = mn0; m1r = mn1;

        float s0 = 0.f, s1 = 0.f;
#pragma unroll
        for (int j = 0; j < 8; j++) {
            sacc[j][0] = __expf(sacc[j][0] - mn0);
            sacc[j][1] = __expf(sacc[j][1] - mn0);
            sacc[j][2] = __expf(sacc[j][2] - mn1);
            sacc[j][3] = __expf(sacc[j][3] - mn1);
            s0 += sacc[j][0] + sacc[j][1];
            s1 += sacc[j][2] + sacc[j][3];
        }
        s0 += __shfl_xor_sync(0xffffffffu, s0, 1);
        s0 += __shfl_xor_sync(0xffffffffu, s0, 2);
        s1 += __shfl_xor_sync(0xffffffffu, s1, 1);
        s1 += __shfl_xor_sync(0xffffffffu, s1, 2);
        l0r = l0r * a0 + s0;
        l1r = l1r * a1 + s1;
#pragma unroll
        for (int j = 0; j < 8; j++) {
            oacc[j][0] *= a0; oacc[j][1] *= a0;
            oacc[j][2] *= a1; oacc[j][3] *= a1;
        }

#pragma unroll
        for (int jp2 = 0; jp2 < 4; jp2++) {
            uint32_t ap_h[4], ap_l[4];
#pragma unroll
            for (int half = 0; half < 2; half++) {
                const float* c = sacc[2 * jp2 + half];
                __half2 h01 = __float22half2_rn(make_float2(c[0], c[1]));
                __half2 h23 = __float22half2_rn(make_float2(c[2], c[3]));
                float2 f01 = __half22float2(h01);
                float2 f23 = __half22float2(h23);
                __half2 l01 = __float22half2_rn(make_float2(c[0] - f01.x, c[1] - f01.y));
                __half2 l23 = __float22half2_rn(make_float2(c[2] - f23.x, c[3] - f23.y));
                ap_h[half == 0 ? 0 : 2] = *reinterpret_cast<uint32_t*>(&h01);
                ap_h[half == 0 ? 1 : 3] = *reinterpret_cast<uint32_t*>(&h23);
                ap_l[half == 0 ? 0 : 2] = *reinterpret_cast<uint32_t*>(&l01);
                ap_l[half == 0 ? 1 : 3] = *reinterpret_cast<uint32_t*>(&l23);
            }
            const uint32_t vrow =
                (uint32_t)((jp2 * 16 + v_row_base) * VPITCH * 2 + v_col_half * 2);
#pragma unroll
            for (int jp = 0; jp < 4; jp++) {
                uint32_t b0, b1, b2, b3;
                ldsm_x4_trans(b0, b1, b2, b3, vhb + vrow + jp * 32);
                mma16h(oacc[jp * 2 + 0], ap_l, b0, b1);
                mma16h(oacc[jp * 2 + 0], ap_h, b0, b1);
                mma16h(oacc[jp * 2 + 1], ap_l, b2, b3);
                mma16h(oacc[jp * 2 + 1], ap_h, b2, b3);
            }
        }
    }

    const float i0 = 1.f / l0r;
    const float i1 = 1.f / l1r;
    const int r0 = q0 + qb + g;
    const int r1 = r0 + 8;
#pragma unroll
    for (int j = 0; j < 8; j++) {
        const int col = hh * 64 + j * 8 + 2 * t;
        float y0 = oacc[j][0] * i0, y1 = oacc[j][1] * i0;
        float y2 = oacc[j][2] * i1, y3 = oacc[j][3] * i1;
        __half2 H0 = __float22half2_rn(make_float2(y0, y1));
        float2 F0 = __half22float2(H0);
        __half2 L0 = __float22half2_rn(make_float2(y0 - F0.x, y1 - F0.y));
        __half2 H1 = __float22half2_rn(make_float2(y2, y3));
        float2 F1 = __half22float2(H1);
        __half2 L1 = __float22half2_rn(make_float2(y2 - F1.x, y3 - F1.y));
        const size_t o0 = ((size_t)bb * Sv + r0) * Hv + col;
        const size_t o1 = ((size_t)bb * Sv + r1) * Hv + col;
        *reinterpret_cast<__half2*>(&g_aoh[o0]) = H0;
        *reinterpret_cast<__half2*>(&g_aol[o0]) = L0;
        *reinterpret_cast<__half2*>(&g_aoh[o1]) = H1;
        *reinterpret_cast<__half2*>(&g_aol[o1]) = L1;
    }
}

// ---------------------------------------------------------------------------
extern "C" void kernel_launch(void* const* d_in, const int* in_sizes, int n_in,
                              void* d_out, int out_size)
{
    const float* hs   = (const float*)d_in[0];
    const int*   mask = (const int*)d_in[1];
    const float* Wq   = (const float*)d_in[2];
    const float* Wk   = (const float*)d_in[3];
    const float* Wv   = (const float*)d_in[4];
    const float* Wo   = (const float*)d_in[5];
    float*       out  = (float*)d_out;

    cudaFuncSetAttribute(proj_qk, cudaFuncAttributeMaxDynamicSharedMemorySize, QK_SMEM);
    cudaFuncSetAttribute(proj_v,  cudaFuncAttributeMaxDynamicSharedMemorySize, GEMM_O_SMEM);
    cudaFuncSetAttribute(proj_o,  cudaFuncAttributeMaxDynamicSharedMemorySize, GEMM_O_SMEM);
    cudaFuncSetAttribute(attn_mma, cudaFuncAttributeMaxDynamicSharedMemorySize, ATTN_SMEM);

    split_hidden<<<Mv * Hv / 1024, 256>>>(hs);
    split_wqk<<<dim3(Hv * Hv / 1024, 1, 2), 256>>>(Wq, Wk);
    cvt_wvo<<<dim3(Hv * Hv / 1024, 1, 2), 256>>>(Wv, Wo);

    proj_qk<<<dim3(Hv / 64, Mv / 128, 2), 256, QK_SMEM>>>();
    proj_v<<<dim3(Hv / 128, Mv / 128), 256, GEMM_O_SMEM>>>();

    attn_mma<<<dim3(Sv / 128, NHv, Bv), 256, ATTN_SMEM>>>(mask);

    proj_o<<<dim3(Hv / 128, Mv / 128), 256, GEMM_O_SMEM>>>(out);
}